// round 3
// baseline (speedup 1.0000x reference)
#include <cuda_runtime.h>
#include <cuda_bf16.h>
#include <cstdint>

#define D_MODEL 1024
#define NHEADS  16
#define HDIM    64
#define BATCH   2
#define SEQ     2048
#define NROWS   (BATCH * SEQ)     // 4096
#define KDIM    D_MODEL

// ---------------------------------------------------------------------------
// Scratch (device globals: no allocation allowed)
// ---------------------------------------------------------------------------
__device__ float g_Q [NROWS * D_MODEL];
__device__ float g_K [NROWS * D_MODEL];
__device__ float g_AO[NROWS * D_MODEL];

__device__ __nv_bfloat16 g_Hhi [NROWS * D_MODEL];
__device__ __nv_bfloat16 g_Hlo [NROWS * D_MODEL];
__device__ __nv_bfloat16 g_AOhi[NROWS * D_MODEL];
__device__ __nv_bfloat16 g_AOlo[NROWS * D_MODEL];
__device__ __nv_bfloat16 g_Wqhi[D_MODEL * D_MODEL];
__device__ __nv_bfloat16 g_Wqlo[D_MODEL * D_MODEL];
__device__ __nv_bfloat16 g_Wkhi[D_MODEL * D_MODEL];
__device__ __nv_bfloat16 g_Wklo[D_MODEL * D_MODEL];
__device__ __nv_bfloat16 g_Wohi[D_MODEL * D_MODEL];
__device__ __nv_bfloat16 g_Wolo[D_MODEL * D_MODEL];

// ---------------------------------------------------------------------------
// warp-MMA helpers (portable sm_80+ path; sm_103 target has no tcgen05)
// ---------------------------------------------------------------------------
__device__ __forceinline__ uint32_t smem_to_u32(const void* p) {
    uint32_t a;
    asm("{ .reg .u64 t; cvta.to.shared.u64 t, %1; cvt.u32.u64 %0, t; }"
        : "=r"(a) : "l"(p));
    return a;
}

__device__ __forceinline__ void ldsm_x4(uint32_t& r0, uint32_t& r1,
                                        uint32_t& r2, uint32_t& r3, uint32_t addr) {
    asm volatile("ldmatrix.sync.aligned.m8n8.x4.shared.b16 {%0,%1,%2,%3}, [%4];"
                 : "=r"(r0), "=r"(r1), "=r"(r2), "=r"(r3) : "r"(addr));
}

__device__ __forceinline__ void mma16816(float* c, const uint32_t* a,
                                         const uint32_t* b) {
    asm volatile(
        "mma.sync.aligned.m16n8k16.row.col.f32.bf16.bf16.f32 "
        "{%0,%1,%2,%3}, {%4,%5,%6,%7}, {%8,%9}, {%0,%1,%2,%3};"
        : "+f"(c[0]), "+f"(c[1]), "+f"(c[2]), "+f"(c[3])
        : "r"(a[0]), "r"(a[1]), "r"(a[2]), "r"(a[3]), "r"(b[0]), "r"(b[1]));
}

// ---------------------------------------------------------------------------
// fp32 -> (bf16 hi, bf16 lo) split. n4 = count of float4 groups.
// ---------------------------------------------------------------------------
__global__ __launch_bounds__(256)
void split_kernel(const float4* __restrict__ src,
                  uint2* __restrict__ hi, uint2* __restrict__ lo, int n4)
{
    int i = blockIdx.x * blockDim.x + threadIdx.x;
    if (i >= n4) return;
    float4 v = src[i];
    uint32_t h0 = (uint32_t)__bfloat16_as_ushort(__float2bfloat16(v.x));
    uint32_t h1 = (uint32_t)__bfloat16_as_ushort(__float2bfloat16(v.y));
    uint32_t h2 = (uint32_t)__bfloat16_as_ushort(__float2bfloat16(v.z));
    uint32_t h3 = (uint32_t)__bfloat16_as_ushort(__float2bfloat16(v.w));
    float r0 = v.x - __uint_as_float(h0 << 16);
    float r1 = v.y - __uint_as_float(h1 << 16);
    float r2 = v.z - __uint_as_float(h2 << 16);
    float r3 = v.w - __uint_as_float(h3 << 16);
    uint32_t l0 = (uint32_t)__bfloat16_as_ushort(__float2bfloat16(r0));
    uint32_t l1 = (uint32_t)__bfloat16_as_ushort(__float2bfloat16(r1));
    uint32_t l2 = (uint32_t)__bfloat16_as_ushort(__float2bfloat16(r2));
    uint32_t l3 = (uint32_t)__bfloat16_as_ushort(__float2bfloat16(r3));
    hi[i] = make_uint2(h0 | (h1 << 16), h2 | (h3 << 16));
    lo[i] = make_uint2(l0 | (l1 << 16), l2 | (l3 << 16));
}

// ---------------------------------------------------------------------------
// HMMA GEMM: C[4096,1024] = A[4096,1024] @ W[1024,1024]^T + bias
// 3-pass bf16 split: D += Ahi*Whi + Ahi*Wlo + Alo*Whi  (fp32 accumulate)
// CTA 128x128, BK=32, 256 threads = 8 warps (2m x 4n), warp tile 64x32.
// ---------------------------------------------------------------------------
#define BM 128
#define BN 128
#define BKK 32
#define LDT 40      // padded row: 40 bf16 = 80 B (stride 5 x 16B, mod 8 -> no LDSM conflicts)

__global__ __launch_bounds__(256, 1)
void mma_gemm_kernel(const __nv_bfloat16* __restrict__ Ahi,
                     const __nv_bfloat16* __restrict__ Alo,
                     const __nv_bfloat16* __restrict__ Whi,
                     const __nv_bfloat16* __restrict__ Wlo,
                     const float* __restrict__ bias,
                     float* __restrict__ C)
{
    __shared__ __nv_bfloat16 sAhi[BM][LDT];
    __shared__ __nv_bfloat16 sAlo[BM][LDT];
    __shared__ __nv_bfloat16 sWhi[BN][LDT];
    __shared__ __nv_bfloat16 sWlo[BN][LDT];
    __shared__ float s_bias[BN];

    const int tid = threadIdx.x;
    const int wid = tid >> 5;
    const int lid = tid & 31;
    const int wm  = wid & 1;          // 2 warps in m
    const int wn  = wid >> 1;         // 4 warps in n
    const int m0  = blockIdx.y * BM;
    const int n0  = blockIdx.x * BN;

    if (tid < BN) s_bias[tid] = bias[n0 + tid];

    // lane decomposition for ldmatrix.x4 addressing
    const int lr   = lid & 7;
    const int half = (lid >> 3) & 1;  // +8 rows
    const int kh   = (lid >> 4) & 1;  // +8 k

    const int mbase = wm * 64;
    const int nbase = wn * 32;

    float acc[4][4][4];
#pragma unroll
    for (int i = 0; i < 4; i++)
#pragma unroll
        for (int j = 0; j < 4; j++)
#pragma unroll
            for (int c = 0; c < 4; c++) acc[i][j][c] = 0.0f;

    const uint32_t uAhi = smem_to_u32(&sAhi[0][0]);
    const uint32_t uAlo = smem_to_u32(&sAlo[0][0]);
    const uint32_t uWhi = smem_to_u32(&sWhi[0][0]);
    const uint32_t uWlo = smem_to_u32(&sWlo[0][0]);

    for (int k0 = 0; k0 < KDIM; k0 += BKK) {
        // ---- global -> smem: 4 tiles of 128 x 32 bf16, 16B chunks ----
#pragma unroll
        for (int it = 0; it < 2; it++) {
            int e   = tid + it * 256;       // 0..511
            int row = e >> 2;               // 0..127
            int c   = e & 3;                // 16B chunk in row (32 bf16 = 4 chunks)
            size_t aoff = (size_t)(m0 + row) * KDIM + k0;
            size_t woff = (size_t)(n0 + row) * KDIM + k0;
            *(uint4*)&sAhi[row][c * 8] = ((const uint4*)(Ahi + aoff))[c];
            *(uint4*)&sAlo[row][c * 8] = ((const uint4*)(Alo + aoff))[c];
            *(uint4*)&sWhi[row][c * 8] = ((const uint4*)(Whi + woff))[c];
            *(uint4*)&sWlo[row][c * 8] = ((const uint4*)(Wlo + woff))[c];
        }
        __syncthreads();

#pragma unroll
        for (int ks = 0; ks < 2; ks++) {
            const int kcol = ks * 16 + kh * 8;

            uint32_t ahi[4][4], alo[4][4];
#pragma unroll
            for (int mt = 0; mt < 4; mt++) {
                int row = mbase + mt * 16 + lr + 8 * half;
                ldsm_x4(ahi[mt][0], ahi[mt][1], ahi[mt][2], ahi[mt][3],
                        uAhi + (uint32_t)(row * LDT + kcol) * 2);
                ldsm_x4(alo[mt][0], alo[mt][1], alo[mt][2], alo[mt][3],
                        uAlo + (uint32_t)(row * LDT + kcol) * 2);
            }

            uint32_t bhi[4][2], blo[4][2];
#pragma unroll
            for (int ntp = 0; ntp < 2; ntp++) {
                int row = nbase + ntp * 16 + lr + 8 * half;
                uint32_t r0, r1, r2, r3;
                ldsm_x4(r0, r1, r2, r3, uWhi + (uint32_t)(row * LDT + kcol) * 2);
                bhi[ntp * 2 + 0][0] = r0; bhi[ntp * 2 + 0][1] = r2;
                bhi[ntp * 2 + 1][0] = r1; bhi[ntp * 2 + 1][1] = r3;
                ldsm_x4(r0, r1, r2, r3, uWlo + (uint32_t)(row * LDT + kcol) * 2);
                blo[ntp * 2 + 0][0] = r0; blo[ntp * 2 + 0][1] = r2;
                blo[ntp * 2 + 1][0] = r1; blo[ntp * 2 + 1][1] = r3;
            }

#pragma unroll
            for (int mt = 0; mt < 4; mt++)
#pragma unroll
                for (int nt = 0; nt < 4; nt++) {
                    mma16816(acc[mt][nt], ahi[mt], bhi[nt]);
                    mma16816(acc[mt][nt], ahi[mt], blo[nt]);
                    mma16816(acc[mt][nt], alo[mt], bhi[nt]);
                }
        }
        __syncthreads();
    }

    // ---- epilogue: c0,c1 -> (row, col..col+1), c2,c3 -> (row+8, ...) ----
    const int erow = lid >> 2;
    const int ecol = (lid & 3) * 2;
#pragma unroll
    for (int mt = 0; mt < 4; mt++) {
#pragma unroll
        for (int nt = 0; nt < 4; nt++) {
            int gm = m0 + mbase + mt * 16 + erow;
            int nc = nbase + nt * 8 + ecol;
            int gn = n0 + nc;
            float2 v0 = { acc[mt][nt][0] + s_bias[nc],
                          acc[mt][nt][1] + s_bias[nc + 1] };
            float2 v1 = { acc[mt][nt][2] + s_bias[nc],
                          acc[mt][nt][3] + s_bias[nc + 1] };
            *(float2*)&C[(size_t)gm * D_MODEL + gn]       = v0;
            *(float2*)&C[(size_t)(gm + 8) * D_MODEL + gn] = v1;
        }
    }
}

// ---------------------------------------------------------------------------
// Flash attention (fp32): thread PAIR per query row; each thread owns 32 dims.
// grid (B*NH, SEQ/128), 256 threads.
// ---------------------------------------------------------------------------
__global__ __launch_bounds__(256, 2)
void attn_kernel(const float* __restrict__ V /* = H */)
{
    __shared__ float Ks[64][64];
    __shared__ float Vs[64][64];

    const int t    = threadIdx.x;
    const int r    = t >> 1;
    const int half = t & 1;
    const int bh   = blockIdx.x;
    const int b    = bh / NHEADS;
    const int h    = bh % NHEADS;
    const int q0   = blockIdx.y * 128;
    const int row  = b * SEQ + q0 + r;
    const float scale = 0.125f;

    float q[32];
    {
        const float4* qp = (const float4*)(g_Q + (size_t)row * D_MODEL + h * HDIM + half * 32);
#pragma unroll
        for (int i = 0; i < 8; i++) {
            float4 v = qp[i];
            q[4*i+0] = v.x * scale; q[4*i+1] = v.y * scale;
            q[4*i+2] = v.z * scale; q[4*i+3] = v.w * scale;
        }
    }

    float o[32];
#pragma unroll
    for (int i = 0; i < 32; i++) o[i] = 0.0f;
    float mmax = -1e30f, l = 0.0f;

    for (int kt = 0; kt < SEQ / 64; kt++) {
        const float4* Kg = (const float4*)(g_K + (size_t)(b * SEQ + kt * 64) * D_MODEL + h * HDIM);
        const float4* Vg = (const float4*)(V   + (size_t)(b * SEQ + kt * 64) * D_MODEL + h * HDIM);
#pragma unroll
        for (int i = 0; i < 4; i++) {
            int e  = t + i * 256;
            int kr = e >> 4;
            int kc = e & 15;
            ((float4*)Ks)[e] = Kg[kr * (D_MODEL / 4) + kc];
            ((float4*)Vs)[e] = Vg[kr * (D_MODEL / 4) + kc];
        }
        __syncthreads();

#pragma unroll 2
        for (int key = 0; key < 64; key++) {
            const float4* kp = (const float4*)&Ks[key][half * 32];
            float s = 0.0f;
#pragma unroll
            for (int i = 0; i < 8; i++) {
                float4 kv = kp[i];
                s += q[4*i+0]*kv.x + q[4*i+1]*kv.y + q[4*i+2]*kv.z + q[4*i+3]*kv.w;
            }
            s += __shfl_xor_sync(0xffffffffu, s, 1);

            if (s > mmax) {
                float c = __expf(mmax - s);
                l *= c;
#pragma unroll
                for (int i = 0; i < 32; i++) o[i] *= c;
                mmax = s;
            }
            float p = __expf(s - mmax);
            l += p;
            const float4* vp = (const float4*)&Vs[key][half * 32];
#pragma unroll
            for (int i = 0; i < 8; i++) {
                float4 vv = vp[i];
                o[4*i+0] += p * vv.x; o[4*i+1] += p * vv.y;
                o[4*i+2] += p * vv.z; o[4*i+3] += p * vv.w;
            }
        }
        __syncthreads();
    }

    const float inv = 1.0f / l;
    float4* op = (float4*)(g_AO + (size_t)row * D_MODEL + h * HDIM + half * 32);
#pragma unroll
    for (int i = 0; i < 8; i++) {
        float4 v;
        v.x = o[4*i+0] * inv; v.y = o[4*i+1] * inv;
        v.z = o[4*i+2] * inv; v.w = o[4*i+3] * inv;
        op[i] = v;
    }
}

// ---------------------------------------------------------------------------
extern "C" void kernel_launch(void* const* d_in, const int* in_sizes, int n_in,
                              void* d_out, int out_size)
{
    (void)in_sizes; (void)n_in; (void)out_size;
    const float* H  = (const float*)d_in[0];
    const float* Wq = (const float*)d_in[1];
    const float* bq = (const float*)d_in[2];
    const float* Wk = (const float*)d_in[3];
    const float* bk = (const float*)d_in[4];
    const float* Wo = (const float*)d_in[5];
    const float* bo = (const float*)d_in[6];
    float* out = (float*)d_out;

    void *p_Hhi, *p_Hlo, *p_AOhi, *p_AOlo;
    void *p_Wqhi, *p_Wqlo, *p_Wkhi, *p_Wklo, *p_Wohi, *p_Wolo;
    void *p_Q, *p_K, *p_AO;
    cudaGetSymbolAddress(&p_Hhi,  g_Hhi);  cudaGetSymbolAddress(&p_Hlo,  g_Hlo);
    cudaGetSymbolAddress(&p_AOhi, g_AOhi); cudaGetSymbolAddress(&p_AOlo, g_AOlo);
    cudaGetSymbolAddress(&p_Wqhi, g_Wqhi); cudaGetSymbolAddress(&p_Wqlo, g_Wqlo);
    cudaGetSymbolAddress(&p_Wkhi, g_Wkhi); cudaGetSymbolAddress(&p_Wklo, g_Wklo);
    cudaGetSymbolAddress(&p_Wohi, g_Wohi); cudaGetSymbolAddress(&p_Wolo, g_Wolo);
    cudaGetSymbolAddress(&p_Q,  g_Q);
    cudaGetSymbolAddress(&p_K,  g_K);
    cudaGetSymbolAddress(&p_AO, g_AO);

    const int nH4 = NROWS * D_MODEL / 4;
    const int nW4 = D_MODEL * D_MODEL / 4;

    // 1) bf16 hi/lo splits of H and weights
    split_kernel<<<nH4 / 256, 256>>>((const float4*)H,  (uint2*)p_Hhi,  (uint2*)p_Hlo,  nH4);
    split_kernel<<<nW4 / 256, 256>>>((const float4*)Wq, (uint2*)p_Wqhi, (uint2*)p_Wqlo, nW4);
    split_kernel<<<nW4 / 256, 256>>>((const float4*)Wk, (uint2*)p_Wkhi, (uint2*)p_Wklo, nW4);
    split_kernel<<<nW4 / 256, 256>>>((const float4*)Wo, (uint2*)p_Wohi, (uint2*)p_Wolo, nW4);

    // 2) Q / K projections (HMMA)
    dim3 ggrid(D_MODEL / BN, NROWS / BM);     // (8, 32)
    mma_gemm_kernel<<<ggrid, 256>>>(
        (const __nv_bfloat16*)p_Hhi, (const __nv_bfloat16*)p_Hlo,
        (const __nv_bfloat16*)p_Wqhi, (const __nv_bfloat16*)p_Wqlo, bq, (float*)p_Q);
    mma_gemm_kernel<<<ggrid, 256>>>(
        (const __nv_bfloat16*)p_Hhi, (const __nv_bfloat16*)p_Hlo,
        (const __nv_bfloat16*)p_Wkhi, (const __nv_bfloat16*)p_Wklo, bk, (float*)p_K);

    // 3) attention (fp32 flash, thread-pair per row)
    dim3 agrid(BATCH * NHEADS, SEQ / 128);    // (32, 16)
    attn_kernel<<<agrid, 256>>>(H);

    // 4) split AO, output projection (HMMA)
    split_kernel<<<nH4 / 256, 256>>>((const float4*)p_AO, (uint2*)p_AOhi, (uint2*)p_AOlo, nH4);
    mma_gemm_kernel<<<ggrid, 256>>>(
        (const __nv_bfloat16*)p_AOhi, (const __nv_bfloat16*)p_AOlo,
        (const __nv_bfloat16*)p_Wohi, (const __nv_bfloat16*)p_Wolo, bo, out);
}

// round 4
// speedup vs baseline: 3.3995x; 3.3995x over previous
#include <cuda_runtime.h>
#include <cuda_bf16.h>
#include <cstdint>

#define D_MODEL 1024
#define NHEADS  16
#define HDIM    64
#define BATCH   2
#define SEQ     2048
#define NROWS   (BATCH * SEQ)     // 4096
#define KDIM    D_MODEL

// softmax scale folded into Q projection: 1/sqrt(64) * log2(e)
#define QK_SCALE 0.1803368801111244f

// ---------------------------------------------------------------------------
// Scratch (device globals)
// ---------------------------------------------------------------------------
__device__ __nv_bfloat16 g_Hhi [NROWS * D_MODEL];
__device__ __nv_bfloat16 g_Hlo [NROWS * D_MODEL];
__device__ __nv_bfloat16 g_Qh  [NROWS * D_MODEL];
__device__ __nv_bfloat16 g_Ql  [NROWS * D_MODEL];
__device__ __nv_bfloat16 g_Kh  [NROWS * D_MODEL];
__device__ __nv_bfloat16 g_Kl  [NROWS * D_MODEL];
__device__ __nv_bfloat16 g_AOh [NROWS * D_MODEL];
__device__ __nv_bfloat16 g_AOl [NROWS * D_MODEL];
__device__ __nv_bfloat16 g_Wqhi[D_MODEL * D_MODEL];
__device__ __nv_bfloat16 g_Wqlo[D_MODEL * D_MODEL];
__device__ __nv_bfloat16 g_Wkhi[D_MODEL * D_MODEL];
__device__ __nv_bfloat16 g_Wklo[D_MODEL * D_MODEL];
__device__ __nv_bfloat16 g_Wohi[D_MODEL * D_MODEL];
__device__ __nv_bfloat16 g_Wolo[D_MODEL * D_MODEL];

// ---------------------------------------------------------------------------
// helpers
// ---------------------------------------------------------------------------
__device__ __forceinline__ uint32_t smem_to_u32(const void* p) {
    uint32_t a;
    asm("{ .reg .u64 t; cvta.to.shared.u64 t, %1; cvt.u32.u64 %0, t; }"
        : "=r"(a) : "l"(p));
    return a;
}
__device__ __forceinline__ void ldsm_x4(uint32_t& r0, uint32_t& r1,
                                        uint32_t& r2, uint32_t& r3, uint32_t addr) {
    asm volatile("ldmatrix.sync.aligned.m8n8.x4.shared.b16 {%0,%1,%2,%3}, [%4];"
                 : "=r"(r0), "=r"(r1), "=r"(r2), "=r"(r3) : "r"(addr));
}
__device__ __forceinline__ void ldsm_x4_t(uint32_t& r0, uint32_t& r1,
                                          uint32_t& r2, uint32_t& r3, uint32_t addr) {
    asm volatile("ldmatrix.sync.aligned.m8n8.x4.trans.shared.b16 {%0,%1,%2,%3}, [%4];"
                 : "=r"(r0), "=r"(r1), "=r"(r2), "=r"(r3) : "r"(addr));
}
__device__ __forceinline__ void mma16816(float* c, const uint32_t* a,
                                         const uint32_t* b) {
    asm volatile(
        "mma.sync.aligned.m16n8k16.row.col.f32.bf16.bf16.f32 "
        "{%0,%1,%2,%3}, {%4,%5,%6,%7}, {%8,%9}, {%0,%1,%2,%3};"
        : "+f"(c[0]), "+f"(c[1]), "+f"(c[2]), "+f"(c[3])
        : "r"(a[0]), "r"(a[1]), "r"(a[2]), "r"(a[3]), "r"(b[0]), "r"(b[1]));
}
__device__ __forceinline__ float ex2f(float x) {
    float r;
    asm("ex2.approx.ftz.f32 %0, %1;" : "=f"(r) : "f"(x));
    return r;
}
__device__ __forceinline__ uint32_t packbf2(float lo, float hi) {
    __nv_bfloat162 t = __floats2bfloat162_rn(lo, hi);
    return *(uint32_t*)&t;
}

// ---------------------------------------------------------------------------
// fp32 -> (bf16 hi, bf16 lo) split
// ---------------------------------------------------------------------------
__global__ __launch_bounds__(256)
void split_kernel(const float4* __restrict__ src,
                  uint2* __restrict__ hi, uint2* __restrict__ lo, int n4)
{
    int i = blockIdx.x * blockDim.x + threadIdx.x;
    if (i >= n4) return;
    float4 v = src[i];
    uint32_t h0 = (uint32_t)__bfloat16_as_ushort(__float2bfloat16(v.x));
    uint32_t h1 = (uint32_t)__bfloat16_as_ushort(__float2bfloat16(v.y));
    uint32_t h2 = (uint32_t)__bfloat16_as_ushort(__float2bfloat16(v.z));
    uint32_t h3 = (uint32_t)__bfloat16_as_ushort(__float2bfloat16(v.w));
    float r0 = v.x - __uint_as_float(h0 << 16);
    float r1 = v.y - __uint_as_float(h1 << 16);
    float r2 = v.z - __uint_as_float(h2 << 16);
    float r3 = v.w - __uint_as_float(h3 << 16);
    uint32_t l0 = (uint32_t)__bfloat16_as_ushort(__float2bfloat16(r0));
    uint32_t l1 = (uint32_t)__bfloat16_as_ushort(__float2bfloat16(r1));
    uint32_t l2 = (uint32_t)__bfloat16_as_ushort(__float2bfloat16(r2));
    uint32_t l3 = (uint32_t)__bfloat16_as_ushort(__float2bfloat16(r3));
    hi[i] = make_uint2(h0 | (h1 << 16), h2 | (h3 << 16));
    lo[i] = make_uint2(l0 | (l1 << 16), l2 | (l3 << 16));
}

// ---------------------------------------------------------------------------
// HMMA GEMM core: C[4096,1024] = A @ W^T + bias  (3-pass bf16 split)
// CTA 128x128, BK=32, 256 threads = 8 warps (2m x 4n).
// Epilogue: if Ch != null, write scale*(acc+bias) as bf16 hi/lo pair; else fp32.
// ---------------------------------------------------------------------------
#define BM 128
#define BN 128
#define BKK 32
#define LDT 40

__device__ __forceinline__ void gemm_core(
    const __nv_bfloat16* __restrict__ Ahi, const __nv_bfloat16* __restrict__ Alo,
    const __nv_bfloat16* __restrict__ Whi, const __nv_bfloat16* __restrict__ Wlo,
    const float* __restrict__ bias, float scale,
    float* __restrict__ Cf, __nv_bfloat16* __restrict__ Ch, __nv_bfloat16* __restrict__ Cl)
{
    __shared__ __nv_bfloat16 sAhi[BM][LDT];
    __shared__ __nv_bfloat16 sAlo[BM][LDT];
    __shared__ __nv_bfloat16 sWhi[BN][LDT];
    __shared__ __nv_bfloat16 sWlo[BN][LDT];
    __shared__ float s_bias[BN];

    const int tid = threadIdx.x;
    const int wid = tid >> 5;
    const int lid = tid & 31;
    const int wm  = wid & 1;
    const int wn  = wid >> 1;
    const int m0  = blockIdx.y * BM;
    const int n0  = blockIdx.x * BN;

    if (tid < BN) s_bias[tid] = bias[n0 + tid];

    const int lr   = lid & 7;
    const int half = (lid >> 3) & 1;
    const int kh   = (lid >> 4) & 1;
    const int mbase = wm * 64;
    const int nbase = wn * 32;

    float acc[4][4][4];
#pragma unroll
    for (int i = 0; i < 4; i++)
#pragma unroll
        for (int j = 0; j < 4; j++)
#pragma unroll
            for (int c = 0; c < 4; c++) acc[i][j][c] = 0.0f;

    const uint32_t uAhi = smem_to_u32(&sAhi[0][0]);
    const uint32_t uAlo = smem_to_u32(&sAlo[0][0]);
    const uint32_t uWhi = smem_to_u32(&sWhi[0][0]);
    const uint32_t uWlo = smem_to_u32(&sWlo[0][0]);

    for (int k0 = 0; k0 < KDIM; k0 += BKK) {
#pragma unroll
        for (int it = 0; it < 2; it++) {
            int e   = tid + it * 256;
            int row = e >> 2;
            int c   = e & 3;
            size_t aoff = (size_t)(m0 + row) * KDIM + k0;
            size_t woff = (size_t)(n0 + row) * KDIM + k0;
            *(uint4*)&sAhi[row][c * 8] = ((const uint4*)(Ahi + aoff))[c];
            *(uint4*)&sAlo[row][c * 8] = ((const uint4*)(Alo + aoff))[c];
            *(uint4*)&sWhi[row][c * 8] = ((const uint4*)(Whi + woff))[c];
            *(uint4*)&sWlo[row][c * 8] = ((const uint4*)(Wlo + woff))[c];
        }
        __syncthreads();

#pragma unroll
        for (int ks = 0; ks < 2; ks++) {
            const int kcol = ks * 16 + kh * 8;

            uint32_t ahi[4][4], alo[4][4];
#pragma unroll
            for (int mt = 0; mt < 4; mt++) {
                int row = mbase + mt * 16 + lr + 8 * half;
                ldsm_x4(ahi[mt][0], ahi[mt][1], ahi[mt][2], ahi[mt][3],
                        uAhi + (uint32_t)(row * LDT + kcol) * 2);
                ldsm_x4(alo[mt][0], alo[mt][1], alo[mt][2], alo[mt][3],
                        uAlo + (uint32_t)(row * LDT + kcol) * 2);
            }
            uint32_t bhi[4][2], blo[4][2];
#pragma unroll
            for (int ntp = 0; ntp < 2; ntp++) {
                int row = nbase + ntp * 16 + lr + 8 * half;
                uint32_t r0, r1, r2, r3;
                ldsm_x4(r0, r1, r2, r3, uWhi + (uint32_t)(row * LDT + kcol) * 2);
                bhi[ntp * 2 + 0][0] = r0; bhi[ntp * 2 + 0][1] = r2;
                bhi[ntp * 2 + 1][0] = r1; bhi[ntp * 2 + 1][1] = r3;
                ldsm_x4(r0, r1, r2, r3, uWlo + (uint32_t)(row * LDT + kcol) * 2);
                blo[ntp * 2 + 0][0] = r0; blo[ntp * 2 + 0][1] = r2;
                blo[ntp * 2 + 1][0] = r1; blo[ntp * 2 + 1][1] = r3;
            }
#pragma unroll
            for (int mt = 0; mt < 4; mt++)
#pragma unroll
                for (int nt = 0; nt < 4; nt++) {
                    mma16816(acc[mt][nt], ahi[mt], bhi[nt]);
                    mma16816(acc[mt][nt], ahi[mt], blo[nt]);
                    mma16816(acc[mt][nt], alo[mt], bhi[nt]);
                }
        }
        __syncthreads();
    }

    const int erow = lid >> 2;
    const int ecol = (lid & 3) * 2;
#pragma unroll
    for (int mt = 0; mt < 4; mt++) {
#pragma unroll
        for (int nt = 0; nt < 4; nt++) {
            int gm = m0 + mbase + mt * 16 + erow;
            int nc = nbase + nt * 8 + ecol;
            int gn = n0 + nc;
            float v0 = (acc[mt][nt][0] + s_bias[nc])     * scale;
            float v1 = (acc[mt][nt][1] + s_bias[nc + 1]) * scale;
            float v2 = (acc[mt][nt][2] + s_bias[nc])     * scale;
            float v3 = (acc[mt][nt][3] + s_bias[nc + 1]) * scale;
            if (Ch) {
                __nv_bfloat16 h0 = __float2bfloat16(v0), h1 = __float2bfloat16(v1);
                __nv_bfloat16 h2 = __float2bfloat16(v2), h3 = __float2bfloat16(v3);
                float l0f = v0 - __bfloat162float(h0), l1f = v1 - __bfloat162float(h1);
                float l2f = v2 - __bfloat162float(h2), l3f = v3 - __bfloat162float(h3);
                *(uint32_t*)&Ch[(size_t)gm * D_MODEL + gn] =
                    (uint32_t)__bfloat16_as_ushort(h0) | ((uint32_t)__bfloat16_as_ushort(h1) << 16);
                *(uint32_t*)&Cl[(size_t)gm * D_MODEL + gn] =
                    (uint32_t)__bfloat16_as_ushort(__float2bfloat16(l0f)) |
                    ((uint32_t)__bfloat16_as_ushort(__float2bfloat16(l1f)) << 16);
                *(uint32_t*)&Ch[(size_t)(gm + 8) * D_MODEL + gn] =
                    (uint32_t)__bfloat16_as_ushort(h2) | ((uint32_t)__bfloat16_as_ushort(h3) << 16);
                *(uint32_t*)&Cl[(size_t)(gm + 8) * D_MODEL + gn] =
                    (uint32_t)__bfloat16_as_ushort(__float2bfloat16(l2f)) |
                    ((uint32_t)__bfloat16_as_ushort(__float2bfloat16(l3f)) << 16);
            } else {
                *(float2*)&Cf[(size_t)gm * D_MODEL + gn]       = make_float2(v0, v1);
                *(float2*)&Cf[(size_t)(gm + 8) * D_MODEL + gn] = make_float2(v2, v3);
            }
        }
    }
}

__global__ __launch_bounds__(256, 1)
void qk_gemm_kernel(const float* __restrict__ bq, const float* __restrict__ bk)
{
    if (blockIdx.z == 0)
        gemm_core(g_Hhi, g_Hlo, g_Wqhi, g_Wqlo, bq, QK_SCALE, nullptr, g_Qh, g_Ql);
    else
        gemm_core(g_Hhi, g_Hlo, g_Wkhi, g_Wklo, bk, 1.0f, nullptr, g_Kh, g_Kl);
}

__global__ __launch_bounds__(256, 1)
void out_gemm_kernel(const float* __restrict__ bo, float* __restrict__ out)
{
    gemm_core(g_AOh, g_AOl, g_Wohi, g_Wolo, bo, 1.0f, out, nullptr, nullptr);
}

// ---------------------------------------------------------------------------
// HMMA flash attention.
// grid (32 = B*NH, 32 = SEQ/64), 128 threads (4 warps). Warp owns 16 q-rows.
// Key tiles of 64. 3-pass bf16 split on QK^T and PV. exp2-based softmax
// (scale folded into Q at projection).
// ---------------------------------------------------------------------------
#define SLDT 72     // padded smem row: 72 bf16 = 144B

__global__ __launch_bounds__(128)
void attn_mma_kernel()
{
    __shared__ __align__(16) __nv_bfloat16 pool[4 * 64 * SLDT];  // 36,864 B
    __nv_bfloat16* sKh = pool;
    __nv_bfloat16* sKl = pool + 64 * SLDT;
    __nv_bfloat16* sVh = pool + 2 * 64 * SLDT;
    __nv_bfloat16* sVl = pool + 3 * 64 * SLDT;

    const int tid = threadIdx.x;
    const int wid = tid >> 5;
    const int lid = tid & 31;
    const int b   = blockIdx.x >> 4;
    const int h   = blockIdx.x & 15;
    const int q0  = blockIdx.y * 64;

    const int lr   = lid & 7;
    const int half = (lid >> 3) & 1;
    const int kh   = (lid >> 4) & 1;

    // ---- stage Q tile (64 x 64, hi/lo) into pool, load frags to regs ----
#pragma unroll
    for (int i = 0; i < 8; i++) {
        int e   = tid + i * 128;            // 0..1023
        int arr = e >> 9;                   // 0=hi, 1=lo
        int rem = e & 511;
        int row = rem >> 3;
        int c   = rem & 7;
        const __nv_bfloat16* src = (arr ? g_Ql : g_Qh)
            + (size_t)(b * SEQ + q0 + row) * D_MODEL + h * HDIM + c * 8;
        *(uint4*)(pool + arr * 64 * SLDT + row * SLDT + c * 8) = *(const uint4*)src;
    }
    __syncthreads();

    uint32_t qh[4][4], ql[4][4];
    {
        const int wr = wid * 16;
        const uint32_t uQh = smem_to_u32(pool);
        const uint32_t uQl = smem_to_u32(pool + 64 * SLDT);
#pragma unroll
        for (int kc = 0; kc < 4; kc++) {
            int row = wr + lr + 8 * half;
            int col = kc * 16 + kh * 8;
            ldsm_x4(qh[kc][0], qh[kc][1], qh[kc][2], qh[kc][3],
                    uQh + (uint32_t)(row * SLDT + col) * 2);
            ldsm_x4(ql[kc][0], ql[kc][1], ql[kc][2], ql[kc][3],
                    uQl + (uint32_t)(row * SLDT + col) * 2);
        }
    }
    __syncthreads();

    float oacc[8][4];
#pragma unroll
    for (int nt = 0; nt < 8; nt++)
#pragma unroll
        for (int c = 0; c < 4; c++) oacc[nt][c] = 0.0f;
    float m0 = -1e30f, m1 = -1e30f, l0 = 0.0f, l1 = 0.0f;

    const uint32_t uKh = smem_to_u32(sKh);
    const uint32_t uKl = smem_to_u32(sKl);
    const uint32_t uVh = smem_to_u32(sVh);
    const uint32_t uVl = smem_to_u32(sVl);

    for (int kt = 0; kt < SEQ / 64; kt++) {
        const int kb = kt * 64;
        // ---- load K,V tiles (hi/lo), 64 x 64 each ----
#pragma unroll
        for (int i = 0; i < 16; i++) {
            int e   = tid + i * 128;        // 0..2047
            int arr = e >> 9;               // 0 Kh, 1 Kl, 2 Vh, 3 Vl
            int rem = e & 511;
            int row = rem >> 3;
            int c   = rem & 7;
            const __nv_bfloat16* gsrc =
                (arr == 0 ? g_Kh : arr == 1 ? g_Kl : arr == 2 ? g_Hhi : g_Hlo)
                + (size_t)(b * SEQ + kb + row) * D_MODEL + h * HDIM + c * 8;
            *(uint4*)(pool + arr * 64 * SLDT + row * SLDT + c * 8) = *(const uint4*)gsrc;
        }
        __syncthreads();

        // ---- S = Q K^T (3-pass) ----
        float S[8][4];
#pragma unroll
        for (int nt = 0; nt < 8; nt++)
#pragma unroll
            for (int c = 0; c < 4; c++) S[nt][c] = 0.0f;

#pragma unroll
        for (int kc = 0; kc < 4; kc++) {
            uint32_t kbh[8][2], kbl[8][2];
#pragma unroll
            for (int ng = 0; ng < 4; ng++) {
                int row = ng * 16 + lr + 8 * half;
                int col = kc * 16 + kh * 8;
                uint32_t r0, r1, r2, r3;
                ldsm_x4(r0, r1, r2, r3, uKh + (uint32_t)(row * SLDT + col) * 2);
                kbh[ng * 2 + 0][0] = r0; kbh[ng * 2 + 0][1] = r2;
                kbh[ng * 2 + 1][0] = r1; kbh[ng * 2 + 1][1] = r3;
                ldsm_x4(r0, r1, r2, r3, uKl + (uint32_t)(row * SLDT + col) * 2);
                kbl[ng * 2 + 0][0] = r0; kbl[ng * 2 + 0][1] = r2;
                kbl[ng * 2 + 1][0] = r1; kbl[ng * 2 + 1][1] = r3;
            }
#pragma unroll
            for (int nt = 0; nt < 8; nt++) {
                mma16816(S[nt], qh[kc], kbh[nt]);
                mma16816(S[nt], qh[kc], kbl[nt]);
                mma16816(S[nt], ql[kc], kbh[nt]);
            }
        }

        // ---- online softmax (rows r=lid>>2 and r+8) ----
        float tm0 = -1e30f, tm1 = -1e30f;
#pragma unroll
        for (int nt = 0; nt < 8; nt++) {
            tm0 = fmaxf(tm0, fmaxf(S[nt][0], S[nt][1]));
            tm1 = fmaxf(tm1, fmaxf(S[nt][2], S[nt][3]));
        }
        tm0 = fmaxf(tm0, __shfl_xor_sync(0xffffffffu, tm0, 1));
        tm0 = fmaxf(tm0, __shfl_xor_sync(0xffffffffu, tm0, 2));
        tm1 = fmaxf(tm1, __shfl_xor_sync(0xffffffffu, tm1, 1));
        tm1 = fmaxf(tm1, __shfl_xor_sync(0xffffffffu, tm1, 2));
        float mn0 = fmaxf(m0, tm0), mn1 = fmaxf(m1, tm1);
        float a0 = ex2f(m0 - mn0), a1 = ex2f(m1 - mn1);

        uint32_t pah[4][4], pal[4][4];
        float rs0 = 0.0f, rs1 = 0.0f;
#pragma unroll
        for (int j = 0; j < 4; j++) {
#pragma unroll
            for (int s = 0; s < 2; s++) {
                int t2 = j * 2 + s;
                float p0 = ex2f(S[t2][0] - mn0);
                float p1 = ex2f(S[t2][1] - mn0);
                float p2 = ex2f(S[t2][2] - mn1);
                float p3 = ex2f(S[t2][3] - mn1);
                rs0 += p0 + p1;
                rs1 += p2 + p3;
                __nv_bfloat16 h0 = __float2bfloat16(p0), h1 = __float2bfloat16(p1);
                __nv_bfloat16 h2 = __float2bfloat16(p2), h3 = __float2bfloat16(p3);
                pah[j][s * 2 + 0] = (uint32_t)__bfloat16_as_ushort(h0) |
                                    ((uint32_t)__bfloat16_as_ushort(h1) << 16);
                pah[j][s * 2 + 1] = (uint32_t)__bfloat16_as_ushort(h2) |
                                    ((uint32_t)__bfloat16_as_ushort(h3) << 16);
                pal[j][s * 2 + 0] = packbf2(p0 - __bfloat162float(h0),
                                            p1 - __bfloat162float(h1));
                pal[j][s * 2 + 1] = packbf2(p2 - __bfloat162float(h2),
                                            p3 - __bfloat162float(h3));
            }
        }
        rs0 += __shfl_xor_sync(0xffffffffu, rs0, 1);
        rs0 += __shfl_xor_sync(0xffffffffu, rs0, 2);
        rs1 += __shfl_xor_sync(0xffffffffu, rs1, 1);
        rs1 += __shfl_xor_sync(0xffffffffu, rs1, 2);
        l0 = l0 * a0 + rs0;
        l1 = l1 * a1 + rs1;
        m0 = mn0; m1 = mn1;
#pragma unroll
        for (int nt = 0; nt < 8; nt++) {
            oacc[nt][0] *= a0; oacc[nt][1] *= a0;
            oacc[nt][2] *= a1; oacc[nt][3] *= a1;
        }

        // ---- O += P V (3-pass); V fragments via ldmatrix.trans ----
#pragma unroll
        for (int kc = 0; kc < 4; kc++) {
            uint32_t vbh[8][2], vbl[8][2];
#pragma unroll
            for (int dg = 0; dg < 4; dg++) {
                int rowk = kc * 16 + lr + 8 * half;
                int dimc = dg * 16 + kh * 8;
                uint32_t r0, r1, r2, r3;
                ldsm_x4_t(r0, r1, r2, r3, uVh + (uint32_t)(rowk * SLDT + dimc) * 2);
                vbh[dg * 2 + 0][0] = r0; vbh[dg * 2 + 0][1] = r1;
                vbh[dg * 2 + 1][0] = r2; vbh[dg * 2 + 1][1] = r3;
                ldsm_x4_t(r0, r1, r2, r3, uVl + (uint32_t)(rowk * SLDT + dimc) * 2);
                vbl[dg * 2 + 0][0] = r0; vbl[dg * 2 + 0][1] = r1;
                vbl[dg * 2 + 1][0] = r2; vbl[dg * 2 + 1][1] = r3;
            }
#pragma unroll
            for (int nt = 0; nt < 8; nt++) {
                mma16816(oacc[nt], pah[kc], vbh[nt]);
                mma16816(oacc[nt], pah[kc], vbl[nt]);
                mma16816(oacc[nt], pal[kc], vbh[nt]);
            }
        }
        __syncthreads();
    }

    // ---- epilogue: normalize, split to bf16 hi/lo, store ----
    const float inv0 = 1.0f / l0;
    const float inv1 = 1.0f / l1;
    const int gr  = b * SEQ + q0 + wid * 16 + (lid >> 2);
    const int col = h * HDIM + (lid & 3) * 2;
#pragma unroll
    for (int nt = 0; nt < 8; nt++) {
        int gc = col + nt * 8;
        float v0 = oacc[nt][0] * inv0, v1 = oacc[nt][1] * inv0;
        float v2 = oacc[nt][2] * inv1, v3 = oacc[nt][3] * inv1;
        __nv_bfloat16 h0 = __float2bfloat16(v0), h1 = __float2bfloat16(v1);
        __nv_bfloat16 h2 = __float2bfloat16(v2), h3 = __float2bfloat16(v3);
        *(uint32_t*)&g_AOh[(size_t)gr * D_MODEL + gc] =
            (uint32_t)__bfloat16_as_ushort(h0) | ((uint32_t)__bfloat16_as_ushort(h1) << 16);
        *(uint32_t*)&g_AOl[(size_t)gr * D_MODEL + gc] =
            packbf2(v0 - __bfloat162float(h0), v1 - __bfloat162float(h1));
        *(uint32_t*)&g_AOh[(size_t)(gr + 8) * D_MODEL + gc] =
            (uint32_t)__bfloat16_as_ushort(h2) | ((uint32_t)__bfloat16_as_ushort(h3) << 16);
        *(uint32_t*)&g_AOl[(size_t)(gr + 8) * D_MODEL + gc] =
            packbf2(v2 - __bfloat162float(h2), v3 - __bfloat162float(h3));
    }
}

// ---------------------------------------------------------------------------
extern "C" void kernel_launch(void* const* d_in, const int* in_sizes, int n_in,
                              void* d_out, int out_size)
{
    (void)in_sizes; (void)n_in; (void)out_size;
    const float* H  = (const float*)d_in[0];
    const float* Wq = (const float*)d_in[1];
    const float* bq = (const float*)d_in[2];
    const float* Wk = (const float*)d_in[3];
    const float* bk = (const float*)d_in[4];
    const float* Wo = (const float*)d_in[5];
    const float* bo = (const float*)d_in[6];
    float* out = (float*)d_out;

    void *p_Hhi, *p_Hlo;
    void *p_Wqhi, *p_Wqlo, *p_Wkhi, *p_Wklo, *p_Wohi, *p_Wolo;
    cudaGetSymbolAddress(&p_Hhi,  g_Hhi);  cudaGetSymbolAddress(&p_Hlo,  g_Hlo);
    cudaGetSymbolAddress(&p_Wqhi, g_Wqhi); cudaGetSymbolAddress(&p_Wqlo, g_Wqlo);
    cudaGetSymbolAddress(&p_Wkhi, g_Wkhi); cudaGetSymbolAddress(&p_Wklo, g_Wklo);
    cudaGetSymbolAddress(&p_Wohi, g_Wohi); cudaGetSymbolAddress(&p_Wolo, g_Wolo);

    const int nH4 = NROWS * D_MODEL / 4;
    const int nW4 = D_MODEL * D_MODEL / 4;

    split_kernel<<<nH4 / 256, 256>>>((const float4*)H,  (uint2*)p_Hhi,  (uint2*)p_Hlo,  nH4);
    split_kernel<<<nW4 / 256, 256>>>((const float4*)Wq, (uint2*)p_Wqhi, (uint2*)p_Wqlo, nW4);
    split_kernel<<<nW4 / 256, 256>>>((const float4*)Wk, (uint2*)p_Wkhi, (uint2*)p_Wklo, nW4);
    split_kernel<<<nW4 / 256, 256>>>((const float4*)Wo, (uint2*)p_Wohi, (uint2*)p_Wolo, nW4);

    dim3 ggrid(D_MODEL / BN, NROWS / BM, 2);   // (8, 32, 2)
    qk_gemm_kernel<<<ggrid, 256>>>(bq, bk);

    dim3 agrid(BATCH * NHEADS, SEQ / 64);      // (32, 32)
    attn_mma_kernel<<<agrid, 128>>>();

    dim3 ogrid(D_MODEL / BN, NROWS / BM, 1);   // (8, 32)
    out_gemm_kernel<<<ogrid, 256>>>(bo, out);
}

// round 5
// speedup vs baseline: 3.7849x; 1.1134x over previous
#include <cuda_runtime.h>
#include <cuda_bf16.h>
#include <cstdint>

#define D_MODEL 1024
#define NHEADS  16
#define HDIM    64
#define BATCH   2
#define SEQ     2048
#define NROWS   (BATCH * SEQ)     // 4096
#define KDIM    D_MODEL

// softmax scale folded into Q projection: 1/sqrt(64) * log2(e)
#define QK_SCALE 0.1803368801111244f

// ---------------------------------------------------------------------------
// Scratch (device globals)
// ---------------------------------------------------------------------------
__device__ __nv_bfloat16 g_Hhi [NROWS * D_MODEL];
__device__ __nv_bfloat16 g_Hlo [NROWS * D_MODEL];
__device__ __nv_bfloat16 g_Qh  [NROWS * D_MODEL];
__device__ __nv_bfloat16 g_Ql  [NROWS * D_MODEL];
__device__ __nv_bfloat16 g_Kh  [NROWS * D_MODEL];
__device__ __nv_bfloat16 g_Kl  [NROWS * D_MODEL];
__device__ __nv_bfloat16 g_AOh [NROWS * D_MODEL];
__device__ __nv_bfloat16 g_AOl [NROWS * D_MODEL];
__device__ __nv_bfloat16 g_Wqhi[D_MODEL * D_MODEL];
__device__ __nv_bfloat16 g_Wqlo[D_MODEL * D_MODEL];
__device__ __nv_bfloat16 g_Wkhi[D_MODEL * D_MODEL];
__device__ __nv_bfloat16 g_Wklo[D_MODEL * D_MODEL];
__device__ __nv_bfloat16 g_Wohi[D_MODEL * D_MODEL];
__device__ __nv_bfloat16 g_Wolo[D_MODEL * D_MODEL];

// ---------------------------------------------------------------------------
// helpers
// ---------------------------------------------------------------------------
__device__ __forceinline__ uint32_t smem_to_u32(const void* p) {
    uint32_t a;
    asm("{ .reg .u64 t; cvta.to.shared.u64 t, %1; cvt.u32.u64 %0, t; }"
        : "=r"(a) : "l"(p));
    return a;
}
__device__ __forceinline__ void ldsm_x4(uint32_t& r0, uint32_t& r1,
                                        uint32_t& r2, uint32_t& r3, uint32_t addr) {
    asm volatile("ldmatrix.sync.aligned.m8n8.x4.shared.b16 {%0,%1,%2,%3}, [%4];"
                 : "=r"(r0), "=r"(r1), "=r"(r2), "=r"(r3) : "r"(addr));
}
__device__ __forceinline__ void ldsm_x4_t(uint32_t& r0, uint32_t& r1,
                                          uint32_t& r2, uint32_t& r3, uint32_t addr) {
    asm volatile("ldmatrix.sync.aligned.m8n8.x4.trans.shared.b16 {%0,%1,%2,%3}, [%4];"
                 : "=r"(r0), "=r"(r1), "=r"(r2), "=r"(r3) : "r"(addr));
}
__device__ __forceinline__ void mma16816(float* c, const uint32_t* a,
                                         const uint32_t* b) {
    asm volatile(
        "mma.sync.aligned.m16n8k16.row.col.f32.bf16.bf16.f32 "
        "{%0,%1,%2,%3}, {%4,%5,%6,%7}, {%8,%9}, {%0,%1,%2,%3};"
        : "+f"(c[0]), "+f"(c[1]), "+f"(c[2]), "+f"(c[3])
        : "r"(a[0]), "r"(a[1]), "r"(a[2]), "r"(a[3]), "r"(b[0]), "r"(b[1]));
}
__device__ __forceinline__ float ex2f(float x) {
    float r;
    asm("ex2.approx.ftz.f32 %0, %1;" : "=f"(r) : "f"(x));
    return r;
}
__device__ __forceinline__ uint32_t packbf2(float lo, float hi) {
    __nv_bfloat162 t = __floats2bfloat162_rn(lo, hi);
    return *(uint32_t*)&t;
}
__device__ __forceinline__ void cp16(uint32_t smem, const void* g) {
    asm volatile("cp.async.cg.shared.global [%0], [%1], 16;"
                 :: "r"(smem), "l"(g) : "memory");
}
#define CP_COMMIT() asm volatile("cp.async.commit_group;" ::: "memory")
#define CP_WAIT0()  asm volatile("cp.async.wait_group 0;" ::: "memory")

// ---------------------------------------------------------------------------
// fp32 -> (bf16 hi, bf16 lo) split
// ---------------------------------------------------------------------------
__global__ __launch_bounds__(256)
void split_kernel(const float4* __restrict__ src,
                  uint2* __restrict__ hi, uint2* __restrict__ lo, int n4)
{
    int i = blockIdx.x * blockDim.x + threadIdx.x;
    if (i >= n4) return;
    float4 v = src[i];
    uint32_t h0 = (uint32_t)__bfloat16_as_ushort(__float2bfloat16(v.x));
    uint32_t h1 = (uint32_t)__bfloat16_as_ushort(__float2bfloat16(v.y));
    uint32_t h2 = (uint32_t)__bfloat16_as_ushort(__float2bfloat16(v.z));
    uint32_t h3 = (uint32_t)__bfloat16_as_ushort(__float2bfloat16(v.w));
    float r0 = v.x - __uint_as_float(h0 << 16);
    float r1 = v.y - __uint_as_float(h1 << 16);
    float r2 = v.z - __uint_as_float(h2 << 16);
    float r3 = v.w - __uint_as_float(h3 << 16);
    uint32_t l0 = (uint32_t)__bfloat16_as_ushort(__float2bfloat16(r0));
    uint32_t l1 = (uint32_t)__bfloat16_as_ushort(__float2bfloat16(r1));
    uint32_t l2 = (uint32_t)__bfloat16_as_ushort(__float2bfloat16(r2));
    uint32_t l3 = (uint32_t)__bfloat16_as_ushort(__float2bfloat16(r3));
    hi[i] = make_uint2(h0 | (h1 << 16), h2 | (h3 << 16));
    lo[i] = make_uint2(l0 | (l1 << 16), l2 | (l3 << 16));
}

// ---------------------------------------------------------------------------
// HMMA GEMM, cp.async double-buffered.
// C[4096,1024] = A @ W^T + bias, 3-pass bf16 split.
// CTA 128x128, BK=32, 256 threads = 8 warps (2m x 4n).
// ---------------------------------------------------------------------------
#define BM 128
#define BN 128
#define BKK 32
#define LDT 40                     // padded row: 80 B (5 x 16B, odd -> LDSM conflict-free)
#define GTILE (BM * LDT * 2)       // 10240 B per tile
#define GST   (4 * GTILE)          // 40960 B per stage
#define GNIT  (KDIM / BKK)         // 32

__device__ __forceinline__ void gemm_core(
    const __nv_bfloat16* __restrict__ Ahi, const __nv_bfloat16* __restrict__ Alo,
    const __nv_bfloat16* __restrict__ Whi, const __nv_bfloat16* __restrict__ Wlo,
    const float* __restrict__ bias, float scale,
    float* __restrict__ Cf, __nv_bfloat16* __restrict__ Ch, __nv_bfloat16* __restrict__ Cl)
{
    extern __shared__ char dsm[];
    __shared__ float s_bias[BN];

    const int tid = threadIdx.x;
    const int wid = tid >> 5;
    const int lid = tid & 31;
    const int wm  = wid & 1;
    const int wn  = wid >> 1;
    const int m0  = blockIdx.y * BM;
    const int n0  = blockIdx.x * BN;

    if (tid < BN) s_bias[tid] = bias[n0 + tid];

    const int lr   = lid & 7;
    const int half = (lid >> 3) & 1;
    const int kh   = (lid >> 4) & 1;
    const int mbase = wm * 64;
    const int nbase = wn * 32;

    const uint32_t smem_base = smem_to_u32(dsm);

    // per-thread load slots: 8 chunks; tile = it>>1, rem = (it&1)*256 + tid
    const int l_rem  = tid;        // combined below per-it
    (void)l_rem;

    float acc[4][4][4];
#pragma unroll
    for (int i = 0; i < 4; i++)
#pragma unroll
        for (int j = 0; j < 4; j++)
#pragma unroll
            for (int c = 0; c < 4; c++) acc[i][j][c] = 0.0f;

    auto load_stage = [&](int k0, int s) {
        uint32_t sb = smem_base + s * GST;
#pragma unroll
        for (int it = 0; it < 8; it++) {
            int tile = it >> 1;
            int rem  = ((it & 1) << 8) + tid;   // 0..511
            int row  = rem >> 2;
            int c    = rem & 3;
            const __nv_bfloat16* g;
            if (tile == 0)      g = Ahi + (size_t)(m0 + row) * KDIM + k0 + c * 8;
            else if (tile == 1) g = Alo + (size_t)(m0 + row) * KDIM + k0 + c * 8;
            else if (tile == 2) g = Whi + (size_t)(n0 + row) * KDIM + k0 + c * 8;
            else                g = Wlo + (size_t)(n0 + row) * KDIM + k0 + c * 8;
            cp16(sb + tile * GTILE + row * (LDT * 2) + c * 16, g);
        }
        CP_COMMIT();
    };

    load_stage(0, 0);

    for (int i = 0; i < GNIT; i++) {
        const int s = i & 1;
        CP_WAIT0();
        __syncthreads();
        if (i + 1 < GNIT) load_stage((i + 1) * BKK, s ^ 1);

        const uint32_t sb   = smem_base + s * GST;
        const uint32_t uAhi = sb;
        const uint32_t uAlo = sb + GTILE;
        const uint32_t uWhi = sb + 2 * GTILE;
        const uint32_t uWlo = sb + 3 * GTILE;

#pragma unroll
        for (int ks = 0; ks < 2; ks++) {
            const int kcol = ks * 16 + kh * 8;

            uint32_t ahi[4][4], alo[4][4];
#pragma unroll
            for (int mt = 0; mt < 4; mt++) {
                int row = mbase + mt * 16 + lr + 8 * half;
                ldsm_x4(ahi[mt][0], ahi[mt][1], ahi[mt][2], ahi[mt][3],
                        uAhi + (uint32_t)(row * LDT + kcol) * 2);
                ldsm_x4(alo[mt][0], alo[mt][1], alo[mt][2], alo[mt][3],
                        uAlo + (uint32_t)(row * LDT + kcol) * 2);
            }
            uint32_t bhi[4][2], blo[4][2];
#pragma unroll
            for (int ntp = 0; ntp < 2; ntp++) {
                int row = nbase + ntp * 16 + lr + 8 * half;
                uint32_t r0, r1, r2, r3;
                ldsm_x4(r0, r1, r2, r3, uWhi + (uint32_t)(row * LDT + kcol) * 2);
                bhi[ntp * 2 + 0][0] = r0; bhi[ntp * 2 + 0][1] = r2;
                bhi[ntp * 2 + 1][0] = r1; bhi[ntp * 2 + 1][1] = r3;
                ldsm_x4(r0, r1, r2, r3, uWlo + (uint32_t)(row * LDT + kcol) * 2);
                blo[ntp * 2 + 0][0] = r0; blo[ntp * 2 + 0][1] = r2;
                blo[ntp * 2 + 1][0] = r1; blo[ntp * 2 + 1][1] = r3;
            }
#pragma unroll
            for (int mt = 0; mt < 4; mt++)
#pragma unroll
                for (int nt = 0; nt < 4; nt++) {
                    mma16816(acc[mt][nt], ahi[mt], bhi[nt]);
                    mma16816(acc[mt][nt], ahi[mt], blo[nt]);
                    mma16816(acc[mt][nt], alo[mt], bhi[nt]);
                }
        }
    }

    const int erow = lid >> 2;
    const int ecol = (lid & 3) * 2;
#pragma unroll
    for (int mt = 0; mt < 4; mt++) {
#pragma unroll
        for (int nt = 0; nt < 4; nt++) {
            int gm = m0 + mbase + mt * 16 + erow;
            int nc = nbase + nt * 8 + ecol;
            int gn = n0 + nc;
            float v0 = (acc[mt][nt][0] + s_bias[nc])     * scale;
            float v1 = (acc[mt][nt][1] + s_bias[nc + 1]) * scale;
            float v2 = (acc[mt][nt][2] + s_bias[nc])     * scale;
            float v3 = (acc[mt][nt][3] + s_bias[nc + 1]) * scale;
            if (Ch) {
                __nv_bfloat16 h0 = __float2bfloat16(v0), h1 = __float2bfloat16(v1);
                __nv_bfloat16 h2 = __float2bfloat16(v2), h3 = __float2bfloat16(v3);
                *(uint32_t*)&Ch[(size_t)gm * D_MODEL + gn] =
                    (uint32_t)__bfloat16_as_ushort(h0) | ((uint32_t)__bfloat16_as_ushort(h1) << 16);
                *(uint32_t*)&Cl[(size_t)gm * D_MODEL + gn] =
                    packbf2(v0 - __bfloat162float(h0), v1 - __bfloat162float(h1));
                *(uint32_t*)&Ch[(size_t)(gm + 8) * D_MODEL + gn] =
                    (uint32_t)__bfloat16_as_ushort(h2) | ((uint32_t)__bfloat16_as_ushort(h3) << 16);
                *(uint32_t*)&Cl[(size_t)(gm + 8) * D_MODEL + gn] =
                    packbf2(v2 - __bfloat162float(h2), v3 - __bfloat162float(h3));
            } else {
                *(float2*)&Cf[(size_t)gm * D_MODEL + gn]       = make_float2(v0, v1);
                *(float2*)&Cf[(size_t)(gm + 8) * D_MODEL + gn] = make_float2(v2, v3);
            }
        }
    }
}

__global__ __launch_bounds__(256, 1)
void qk_gemm_kernel(const float* __restrict__ bq, const float* __restrict__ bk)
{
    if (blockIdx.z == 0)
        gemm_core(g_Hhi, g_Hlo, g_Wqhi, g_Wqlo, bq, QK_SCALE, nullptr, g_Qh, g_Ql);
    else
        gemm_core(g_Hhi, g_Hlo, g_Wkhi, g_Wklo, bk, 1.0f, nullptr, g_Kh, g_Kl);
}

__global__ __launch_bounds__(256, 1)
void out_gemm_kernel(const float* __restrict__ bo, float* __restrict__ out)
{
    gemm_core(g_AOh, g_AOl, g_Wohi, g_Wolo, bo, 1.0f, out, nullptr, nullptr);
}

// ---------------------------------------------------------------------------
// HMMA flash attention, cp.async double-buffered.
// grid (32 = B*NH, 16 = SEQ/128), 256 threads (8 warps), 128 q-rows per CTA.
// ---------------------------------------------------------------------------
#define SLDT 72                        // padded smem row: 144 B (9 x 16B)
#define ATILE (64 * SLDT * 2)          // 9216 B per K/V array
#define AST   (4 * ATILE)              // 36864 B per stage

__global__ __launch_bounds__(256, 1)
void attn_mma_kernel()
{
    extern __shared__ char dsm[];
    __nv_bfloat16* pool = (__nv_bfloat16*)dsm;

    const int tid = threadIdx.x;
    const int wid = tid >> 5;
    const int lid = tid & 31;
    const int b   = blockIdx.x >> 4;
    const int h   = blockIdx.x & 15;
    const int q0  = blockIdx.y * 128;

    const int lr   = lid & 7;
    const int half = (lid >> 3) & 1;
    const int kh   = (lid >> 4) & 1;

    const uint32_t smem_base = smem_to_u32(dsm);

    // ---- stage Q tile (128 x 64, hi/lo) through stage-0 area, extract frags ----
#pragma unroll
    for (int i = 0; i < 8; i++) {
        int e   = tid + i * 256;            // 0..2047
        int arr = e >> 10;                  // 0=hi, 1=lo
        int rem = e & 1023;
        int row = rem >> 3;
        int c   = rem & 7;
        const __nv_bfloat16* src = (arr ? g_Ql : g_Qh)
            + (size_t)(b * SEQ + q0 + row) * D_MODEL + h * HDIM + c * 8;
        *(uint4*)(pool + arr * 128 * SLDT + row * SLDT + c * 8) = *(const uint4*)src;
    }
    __syncthreads();

    uint32_t qh[4][4], ql[4][4];
    {
        const int wr = wid * 16;
        const uint32_t uQh = smem_base;
        const uint32_t uQl = smem_base + 128 * SLDT * 2;
#pragma unroll
        for (int kc = 0; kc < 4; kc++) {
            int row = wr + lr + 8 * half;
            int col = kc * 16 + kh * 8;
            ldsm_x4(qh[kc][0], qh[kc][1], qh[kc][2], qh[kc][3],
                    uQh + (uint32_t)(row * SLDT + col) * 2);
            ldsm_x4(ql[kc][0], ql[kc][1], ql[kc][2], ql[kc][3],
                    uQl + (uint32_t)(row * SLDT + col) * 2);
        }
    }
    __syncthreads();

    float oacc[8][4];
#pragma unroll
    for (int nt = 0; nt < 8; nt++)
#pragma unroll
        for (int c = 0; c < 4; c++) oacc[nt][c] = 0.0f;
    float mx0 = -1e30f, mx1 = -1e30f, l0 = 0.0f, l1 = 0.0f;

    // K/V stage loader: arrays {Kh, Kl, Vh(=Hhi), Vl(=Hlo)}, 64 x 64 each
    auto load_stage = [&](int kt, int s) {
        const int kb = kt * 64;
        uint32_t sb = smem_base + s * AST;
#pragma unroll
        for (int i = 0; i < 8; i++) {
            int arr = i >> 1;                       // 0..3
            int rem = ((i & 1) << 8) + tid;         // 0..511
            int row = rem >> 3;
            int c   = rem & 7;
            const __nv_bfloat16* g =
                (arr == 0 ? g_Kh : arr == 1 ? g_Kl : arr == 2 ? g_Hhi : g_Hlo)
                + (size_t)(b * SEQ + kb + row) * D_MODEL + h * HDIM + c * 8;
            cp16(sb + arr * ATILE + row * (SLDT * 2) + c * 16, g);
        }
        CP_COMMIT();
    };

    load_stage(0, 0);

    for (int kt = 0; kt < SEQ / 64; kt++) {
        const int s = kt & 1;
        CP_WAIT0();
        __syncthreads();
        if (kt + 1 < SEQ / 64) load_stage(kt + 1, s ^ 1);

        const uint32_t sb  = smem_base + s * AST;
        const uint32_t uKh = sb;
        const uint32_t uKl = sb + ATILE;
        const uint32_t uVh = sb + 2 * ATILE;
        const uint32_t uVl = sb + 3 * ATILE;

        // ---- S = Q K^T (3-pass) ----
        float S[8][4];
#pragma unroll
        for (int nt = 0; nt < 8; nt++)
#pragma unroll
            for (int c = 0; c < 4; c++) S[nt][c] = 0.0f;

#pragma unroll
        for (int kc = 0; kc < 4; kc++) {
            uint32_t kbh[8][2], kbl[8][2];
#pragma unroll
            for (int ng = 0; ng < 4; ng++) {
                int row = ng * 16 + lr + 8 * half;
                int col = kc * 16 + kh * 8;
                uint32_t r0, r1, r2, r3;
                ldsm_x4(r0, r1, r2, r3, uKh + (uint32_t)(row * SLDT + col) * 2);
                kbh[ng * 2 + 0][0] = r0; kbh[ng * 2 + 0][1] = r2;
                kbh[ng * 2 + 1][0] = r1; kbh[ng * 2 + 1][1] = r3;
                ldsm_x4(r0, r1, r2, r3, uKl + (uint32_t)(row * SLDT + col) * 2);
                kbl[ng * 2 + 0][0] = r0; kbl[ng * 2 + 0][1] = r2;
                kbl[ng * 2 + 1][0] = r1; kbl[ng * 2 + 1][1] = r3;
            }
#pragma unroll
            for (int nt = 0; nt < 8; nt++) {
                mma16816(S[nt], qh[kc], kbh[nt]);
                mma16816(S[nt], qh[kc], kbl[nt]);
                mma16816(S[nt], ql[kc], kbh[nt]);
            }
        }

        // ---- online softmax ----
        float tm0 = -1e30f, tm1 = -1e30f;
#pragma unroll
        for (int nt = 0; nt < 8; nt++) {
            tm0 = fmaxf(tm0, fmaxf(S[nt][0], S[nt][1]));
            tm1 = fmaxf(tm1, fmaxf(S[nt][2], S[nt][3]));
        }
        tm0 = fmaxf(tm0, __shfl_xor_sync(0xffffffffu, tm0, 1));
        tm0 = fmaxf(tm0, __shfl_xor_sync(0xffffffffu, tm0, 2));
        tm1 = fmaxf(tm1, __shfl_xor_sync(0xffffffffu, tm1, 1));
        tm1 = fmaxf(tm1, __shfl_xor_sync(0xffffffffu, tm1, 2));
        float mn0 = fmaxf(mx0, tm0), mn1 = fmaxf(mx1, tm1);
        float a0 = ex2f(mx0 - mn0), a1 = ex2f(mx1 - mn1);

        uint32_t pah[4][4], pal[4][4];
        float rs0 = 0.0f, rs1 = 0.0f;
#pragma unroll
        for (int j = 0; j < 4; j++) {
#pragma unroll
            for (int sgrp = 0; sgrp < 2; sgrp++) {
                int t2 = j * 2 + sgrp;
                float p0 = ex2f(S[t2][0] - mn0);
                float p1 = ex2f(S[t2][1] - mn0);
                float p2 = ex2f(S[t2][2] - mn1);
                float p3 = ex2f(S[t2][3] - mn1);
                rs0 += p0 + p1;
                rs1 += p2 + p3;
                __nv_bfloat16 h0 = __float2bfloat16(p0), h1 = __float2bfloat16(p1);
                __nv_bfloat16 h2 = __float2bfloat16(p2), h3 = __float2bfloat16(p3);
                pah[j][sgrp * 2 + 0] = (uint32_t)__bfloat16_as_ushort(h0) |
                                       ((uint32_t)__bfloat16_as_ushort(h1) << 16);
                pah[j][sgrp * 2 + 1] = (uint32_t)__bfloat16_as_ushort(h2) |
                                       ((uint32_t)__bfloat16_as_ushort(h3) << 16);
                pal[j][sgrp * 2 + 0] = packbf2(p0 - __bfloat162float(h0),
                                               p1 - __bfloat162float(h1));
                pal[j][sgrp * 2 + 1] = packbf2(p2 - __bfloat162float(h2),
                                               p3 - __bfloat162float(h3));
            }
        }
        rs0 += __shfl_xor_sync(0xffffffffu, rs0, 1);
        rs0 += __shfl_xor_sync(0xffffffffu, rs0, 2);
        rs1 += __shfl_xor_sync(0xffffffffu, rs1, 1);
        rs1 += __shfl_xor_sync(0xffffffffu, rs1, 2);
        l0 = l0 * a0 + rs0;
        l1 = l1 * a1 + rs1;
        mx0 = mn0; mx1 = mn1;
#pragma unroll
        for (int nt = 0; nt < 8; nt++) {
            oacc[nt][0] *= a0; oacc[nt][1] *= a0;
            oacc[nt][2] *= a1; oacc[nt][3] *= a1;
        }

        // ---- O += P V (3-pass) ----
#pragma unroll
        for (int kc = 0; kc < 4; kc++) {
            uint32_t vbh[8][2], vbl[8][2];
#pragma unroll
            for (int dg = 0; dg < 4; dg++) {
                int rowk = kc * 16 + lr + 8 * half;
                int dimc = dg * 16 + kh * 8;
                uint32_t r0, r1, r2, r3;
                ldsm_x4_t(r0, r1, r2, r3, uVh + (uint32_t)(rowk * SLDT + dimc) * 2);
                vbh[dg * 2 + 0][0] = r0; vbh[dg * 2 + 0][1] = r1;
                vbh[dg * 2 + 1][0] = r2; vbh[dg * 2 + 1][1] = r3;
                ldsm_x4_t(r0, r1, r2, r3, uVl + (uint32_t)(rowk * SLDT + dimc) * 2);
                vbl[dg * 2 + 0][0] = r0; vbl[dg * 2 + 0][1] = r1;
                vbl[dg * 2 + 1][0] = r2; vbl[dg * 2 + 1][1] = r3;
            }
#pragma unroll
            for (int nt = 0; nt < 8; nt++) {
                mma16816(oacc[nt], pah[kc], vbh[nt]);
                mma16816(oacc[nt], pah[kc], vbl[nt]);
                mma16816(oacc[nt], pal[kc], vbh[nt]);
            }
        }
    }

    // ---- epilogue ----
    const float inv0 = 1.0f / l0;
    const float inv1 = 1.0f / l1;
    const int gr  = b * SEQ + q0 + wid * 16 + (lid >> 2);
    const int col = h * HDIM + (lid & 3) * 2;
#pragma unroll
    for (int nt = 0; nt < 8; nt++) {
        int gc = col + nt * 8;
        float v0 = oacc[nt][0] * inv0, v1 = oacc[nt][1] * inv0;
        float v2 = oacc[nt][2] * inv1, v3 = oacc[nt][3] * inv1;
        __nv_bfloat16 h0 = __float2bfloat16(v0), h1 = __float2bfloat16(v1);
        __nv_bfloat16 h2 = __float2bfloat16(v2), h3 = __float2bfloat16(v3);
        *(uint32_t*)&g_AOh[(size_t)gr * D_MODEL + gc] =
            (uint32_t)__bfloat16_as_ushort(h0) | ((uint32_t)__bfloat16_as_ushort(h1) << 16);
        *(uint32_t*)&g_AOl[(size_t)gr * D_MODEL + gc] =
            packbf2(v0 - __bfloat162float(h0), v1 - __bfloat162float(h1));
        *(uint32_t*)&g_AOh[(size_t)(gr + 8) * D_MODEL + gc] =
            (uint32_t)__bfloat16_as_ushort(h2) | ((uint32_t)__bfloat16_as_ushort(h3) << 16);
        *(uint32_t*)&g_AOl[(size_t)(gr + 8) * D_MODEL + gc] =
            packbf2(v2 - __bfloat162float(h2), v3 - __bfloat162float(h3));
    }
}

// ---------------------------------------------------------------------------
extern "C" void kernel_launch(void* const* d_in, const int* in_sizes, int n_in,
                              void* d_out, int out_size)
{
    (void)in_sizes; (void)n_in; (void)out_size;
    const float* H  = (const float*)d_in[0];
    const float* Wq = (const float*)d_in[1];
    const float* bq = (const float*)d_in[2];
    const float* Wk = (const float*)d_in[3];
    const float* bk = (const float*)d_in[4];
    const float* Wo = (const float*)d_in[5];
    const float* bo = (const float*)d_in[6];
    float* out = (float*)d_out;

    void *p_Hhi, *p_Hlo;
    void *p_Wqhi, *p_Wqlo, *p_Wkhi, *p_Wklo, *p_Wohi, *p_Wolo;
    cudaGetSymbolAddress(&p_Hhi,  g_Hhi);  cudaGetSymbolAddress(&p_Hlo,  g_Hlo);
    cudaGetSymbolAddress(&p_Wqhi, g_Wqhi); cudaGetSymbolAddress(&p_Wqlo, g_Wqlo);
    cudaGetSymbolAddress(&p_Wkhi, g_Wkhi); cudaGetSymbolAddress(&p_Wklo, g_Wklo);
    cudaGetSymbolAddress(&p_Wohi, g_Wohi); cudaGetSymbolAddress(&p_Wolo, g_Wolo);

    cudaFuncSetAttribute(qk_gemm_kernel,
                         cudaFuncAttributeMaxDynamicSharedMemorySize, 2 * GST);
    cudaFuncSetAttribute(out_gemm_kernel,
                         cudaFuncAttributeMaxDynamicSharedMemorySize, 2 * GST);
    cudaFuncSetAttribute(attn_mma_kernel,
                         cudaFuncAttributeMaxDynamicSharedMemorySize, 2 * AST);

    const int nH4 = NROWS * D_MODEL / 4;
    const int nW4 = D_MODEL * D_MODEL / 4;

    split_kernel<<<nH4 / 256, 256>>>((const float4*)H,  (uint2*)p_Hhi,  (uint2*)p_Hlo,  nH4);
    split_kernel<<<nW4 / 256, 256>>>((const float4*)Wq, (uint2*)p_Wqhi, (uint2*)p_Wqlo, nW4);
    split_kernel<<<nW4 / 256, 256>>>((const float4*)Wk, (uint2*)p_Wkhi, (uint2*)p_Wklo, nW4);
    split_kernel<<<nW4 / 256, 256>>>((const float4*)Wo, (uint2*)p_Wohi, (uint2*)p_Wolo, nW4);

    dim3 ggrid(D_MODEL / BN, NROWS / BM, 2);   // (8, 32, 2)
    qk_gemm_kernel<<<ggrid, 256, 2 * GST>>>(bq, bk);

    dim3 agrid(BATCH * NHEADS, SEQ / 128);     // (32, 16)
    attn_mma_kernel<<<agrid, 256, 2 * AST>>>();

    dim3 ogrid(D_MODEL / BN, NROWS / BM, 1);   // (8, 32)
    out_gemm_kernel<<<ogrid, 256, 2 * GST>>>(bo, out);
}

// round 6
// speedup vs baseline: 4.4261x; 1.1694x over previous
#include <cuda_runtime.h>
#include <cuda_fp16.h>
#include <cstdint>

#define D_MODEL 1024
#define NHEADS  16
#define HDIM    64
#define BATCH   2
#define SEQ     2048
#define NROWS   (BATCH * SEQ)     // 4096
#define KDIM    D_MODEL

// softmax scale folded into Q projection: 1/sqrt(64) * log2(e)
#define QK_SCALE 0.1803368801111244f

// ---------------------------------------------------------------------------
// Scratch (device globals) — all fp16 hi/lo pairs
// ---------------------------------------------------------------------------
__device__ __half g_Hhi [NROWS * D_MODEL];
__device__ __half g_Hlo [NROWS * D_MODEL];
__device__ __half g_Qh  [NROWS * D_MODEL];
__device__ __half g_Ql  [NROWS * D_MODEL];
__device__ __half g_Kh  [NROWS * D_MODEL];
__device__ __half g_Kl  [NROWS * D_MODEL];
__device__ __half g_AOh [NROWS * D_MODEL];
__device__ __half g_AOl [NROWS * D_MODEL];
__device__ __half g_Wqhi[D_MODEL * D_MODEL];
__device__ __half g_Wqlo[D_MODEL * D_MODEL];
__device__ __half g_Wkhi[D_MODEL * D_MODEL];
__device__ __half g_Wklo[D_MODEL * D_MODEL];
__device__ __half g_Wohi[D_MODEL * D_MODEL];
__device__ __half g_Wolo[D_MODEL * D_MODEL];

// ---------------------------------------------------------------------------
// helpers
// ---------------------------------------------------------------------------
__device__ __forceinline__ uint32_t smem_to_u32(const void* p) {
    uint32_t a;
    asm("{ .reg .u64 t; cvta.to.shared.u64 t, %1; cvt.u32.u64 %0, t; }"
        : "=r"(a) : "l"(p));
    return a;
}
__device__ __forceinline__ void ldsm_x4(uint32_t& r0, uint32_t& r1,
                                        uint32_t& r2, uint32_t& r3, uint32_t addr) {
    asm volatile("ldmatrix.sync.aligned.m8n8.x4.shared.b16 {%0,%1,%2,%3}, [%4];"
                 : "=r"(r0), "=r"(r1), "=r"(r2), "=r"(r3) : "r"(addr));
}
__device__ __forceinline__ void ldsm_x4_t(uint32_t& r0, uint32_t& r1,
                                          uint32_t& r2, uint32_t& r3, uint32_t addr) {
    asm volatile("ldmatrix.sync.aligned.m8n8.x4.trans.shared.b16 {%0,%1,%2,%3}, [%4];"
                 : "=r"(r0), "=r"(r1), "=r"(r2), "=r"(r3) : "r"(addr));
}
__device__ __forceinline__ void mma16816(float* c, const uint32_t* a,
                                         const uint32_t* b) {
    asm volatile(
        "mma.sync.aligned.m16n8k16.row.col.f32.f16.f16.f32 "
        "{%0,%1,%2,%3}, {%4,%5,%6,%7}, {%8,%9}, {%0,%1,%2,%3};"
        : "+f"(c[0]), "+f"(c[1]), "+f"(c[2]), "+f"(c[3])
        : "r"(a[0]), "r"(a[1]), "r"(a[2]), "r"(a[3]), "r"(b[0]), "r"(b[1]));
}
__device__ __forceinline__ float ex2f(float x) {
    float r;
    asm("ex2.approx.ftz.f32 %0, %1;" : "=f"(r) : "f"(x));
    return r;
}
__device__ __forceinline__ uint32_t packh2(float a, float b) {
    __half2 t = __floats2half2_rn(a, b);
    return *(uint32_t*)&t;
}
__device__ __forceinline__ void cp16(uint32_t smem, const void* g) {
    asm volatile("cp.async.cg.shared.global [%0], [%1], 16;"
                 :: "r"(smem), "l"(g) : "memory");
}
#define CP_COMMIT() asm volatile("cp.async.commit_group;" ::: "memory")
#define CP_WAIT0()  asm volatile("cp.async.wait_group 0;" ::: "memory")

// ---------------------------------------------------------------------------
// fp32 -> (fp16 hi, fp16 lo) split, 4 tensors in one launch
// ---------------------------------------------------------------------------
__device__ __forceinline__ void split4_do(const float4* src, uint2* hi, uint2* lo, int i)
{
    float4 v = src[i];
    __half h0 = __float2half_rn(v.x), h1 = __float2half_rn(v.y);
    __half h2 = __float2half_rn(v.z), h3 = __float2half_rn(v.w);
    float r0 = v.x - __half2float(h0), r1 = v.y - __half2float(h1);
    float r2 = v.z - __half2float(h2), r3 = v.w - __half2float(h3);
    hi[i] = make_uint2(
        (uint32_t)__half_as_ushort(h0) | ((uint32_t)__half_as_ushort(h1) << 16),
        (uint32_t)__half_as_ushort(h2) | ((uint32_t)__half_as_ushort(h3) << 16));
    lo[i] = make_uint2(packh2(r0, r1), packh2(r2, r3));
}

__global__ __launch_bounds__(256)
void split4_kernel(const float4* s0, uint2* h0, uint2* l0, int n0,
                   const float4* s1, uint2* h1, uint2* l1, int n1,
                   const float4* s2, uint2* h2, uint2* l2, int n2,
                   const float4* s3, uint2* h3, uint2* l3, int n3)
{
    int i = blockIdx.x * blockDim.x + threadIdx.x;
    if (i < n0) { split4_do(s0, h0, l0, i); return; }
    i -= n0;
    if (i < n1) { split4_do(s1, h1, l1, i); return; }
    i -= n1;
    if (i < n2) { split4_do(s2, h2, l2, i); return; }
    i -= n2;
    if (i < n3) { split4_do(s3, h3, l3, i); }
}

// ---------------------------------------------------------------------------
// HMMA GEMM, cp.async double-buffered, fp16 3-pass split.
// C[4096,1024] = A @ W^T + bias. CTA 128x128, BK=32, 256 threads (8 warps).
// ---------------------------------------------------------------------------
#define BM 128
#define BN 128
#define BKK 32
#define LDT 40                     // 80 B row (5 x 16B) -> LDSM conflict-free
#define GTILE (BM * LDT * 2)       // 10240 B
#define GST   (4 * GTILE)          // 40960 B per stage
#define GNIT  (KDIM / BKK)         // 32

__device__ __forceinline__ void gemm_core(
    const __half* __restrict__ Ahi, const __half* __restrict__ Alo,
    const __half* __restrict__ Whi, const __half* __restrict__ Wlo,
    const float* __restrict__ bias, float scale,
    float* __restrict__ Cf, __half* __restrict__ Ch, __half* __restrict__ Cl)
{
    extern __shared__ char dsm[];
    __shared__ float s_bias[BN];

    const int tid = threadIdx.x;
    const int wid = tid >> 5;
    const int lid = tid & 31;
    const int wm  = wid & 1;
    const int wn  = wid >> 1;
    const int m0  = blockIdx.y * BM;
    const int n0  = blockIdx.x * BN;

    if (tid < BN) s_bias[tid] = bias[n0 + tid];

    const int lr   = lid & 7;
    const int half2_ = (lid >> 3) & 1;
    const int kh   = (lid >> 4) & 1;
    const int mbase = wm * 64;
    const int nbase = wn * 32;

    const uint32_t smem_base = smem_to_u32(dsm);

    float acc[4][4][4];
#pragma unroll
    for (int i = 0; i < 4; i++)
#pragma unroll
        for (int j = 0; j < 4; j++)
#pragma unroll
            for (int c = 0; c < 4; c++) acc[i][j][c] = 0.0f;

    auto load_stage = [&](int k0, int s) {
        uint32_t sb = smem_base + s * GST;
#pragma unroll
        for (int it = 0; it < 8; it++) {
            int tile = it >> 1;
            int rem  = ((it & 1) << 8) + tid;
            int row  = rem >> 2;
            int c    = rem & 3;
            const __half* g;
            if (tile == 0)      g = Ahi + (size_t)(m0 + row) * KDIM + k0 + c * 8;
            else if (tile == 1) g = Alo + (size_t)(m0 + row) * KDIM + k0 + c * 8;
            else if (tile == 2) g = Whi + (size_t)(n0 + row) * KDIM + k0 + c * 8;
            else                g = Wlo + (size_t)(n0 + row) * KDIM + k0 + c * 8;
            cp16(sb + tile * GTILE + row * (LDT * 2) + c * 16, g);
        }
        CP_COMMIT();
    };

    load_stage(0, 0);

    for (int i = 0; i < GNIT; i++) {
        const int s = i & 1;
        CP_WAIT0();
        __syncthreads();
        if (i + 1 < GNIT) load_stage((i + 1) * BKK, s ^ 1);

        const uint32_t sb   = smem_base + s * GST;
        const uint32_t uAhi = sb;
        const uint32_t uAlo = sb + GTILE;
        const uint32_t uWhi = sb + 2 * GTILE;
        const uint32_t uWlo = sb + 3 * GTILE;

#pragma unroll
        for (int ks = 0; ks < 2; ks++) {
            const int kcol = ks * 16 + kh * 8;

            uint32_t ahi[4][4], alo[4][4];
#pragma unroll
            for (int mt = 0; mt < 4; mt++) {
                int row = mbase + mt * 16 + lr + 8 * half2_;
                ldsm_x4(ahi[mt][0], ahi[mt][1], ahi[mt][2], ahi[mt][3],
                        uAhi + (uint32_t)(row * LDT + kcol) * 2);
                ldsm_x4(alo[mt][0], alo[mt][1], alo[mt][2], alo[mt][3],
                        uAlo + (uint32_t)(row * LDT + kcol) * 2);
            }
            uint32_t bhi[4][2], blo[4][2];
#pragma unroll
            for (int ntp = 0; ntp < 2; ntp++) {
                int row = nbase + ntp * 16 + lr + 8 * half2_;
                uint32_t r0, r1, r2, r3;
                ldsm_x4(r0, r1, r2, r3, uWhi + (uint32_t)(row * LDT + kcol) * 2);
                bhi[ntp * 2 + 0][0] = r0; bhi[ntp * 2 + 0][1] = r2;
                bhi[ntp * 2 + 1][0] = r1; bhi[ntp * 2 + 1][1] = r3;
                ldsm_x4(r0, r1, r2, r3, uWlo + (uint32_t)(row * LDT + kcol) * 2);
                blo[ntp * 2 + 0][0] = r0; blo[ntp * 2 + 0][1] = r2;
                blo[ntp * 2 + 1][0] = r1; blo[ntp * 2 + 1][1] = r3;
            }
#pragma unroll
            for (int mt = 0; mt < 4; mt++)
#pragma unroll
                for (int nt = 0; nt < 4; nt++) {
                    mma16816(acc[mt][nt], ahi[mt], bhi[nt]);
                    mma16816(acc[mt][nt], ahi[mt], blo[nt]);
                    mma16816(acc[mt][nt], alo[mt], bhi[nt]);
                }
        }
    }

    const int erow = lid >> 2;
    const int ecol = (lid & 3) * 2;
#pragma unroll
    for (int mt = 0; mt < 4; mt++) {
#pragma unroll
        for (int nt = 0; nt < 4; nt++) {
            int gm = m0 + mbase + mt * 16 + erow;
            int nc = nbase + nt * 8 + ecol;
            int gn = n0 + nc;
            float v0 = (acc[mt][nt][0] + s_bias[nc])     * scale;
            float v1 = (acc[mt][nt][1] + s_bias[nc + 1]) * scale;
            float v2 = (acc[mt][nt][2] + s_bias[nc])     * scale;
            float v3 = (acc[mt][nt][3] + s_bias[nc + 1]) * scale;
            if (Ch) {
                __half h0 = __float2half_rn(v0), h1 = __float2half_rn(v1);
                __half h2 = __float2half_rn(v2), h3 = __float2half_rn(v3);
                *(uint32_t*)&Ch[(size_t)gm * D_MODEL + gn] =
                    (uint32_t)__half_as_ushort(h0) | ((uint32_t)__half_as_ushort(h1) << 16);
                *(uint32_t*)&Cl[(size_t)gm * D_MODEL + gn] =
                    packh2(v0 - __half2float(h0), v1 - __half2float(h1));
                *(uint32_t*)&Ch[(size_t)(gm + 8) * D_MODEL + gn] =
                    (uint32_t)__half_as_ushort(h2) | ((uint32_t)__half_as_ushort(h3) << 16);
                *(uint32_t*)&Cl[(size_t)(gm + 8) * D_MODEL + gn] =
                    packh2(v2 - __half2float(h2), v3 - __half2float(h3));
            } else {
                *(float2*)&Cf[(size_t)gm * D_MODEL + gn]       = make_float2(v0, v1);
                *(float2*)&Cf[(size_t)(gm + 8) * D_MODEL + gn] = make_float2(v2, v3);
            }
        }
    }
}

__global__ __launch_bounds__(256, 2)
void qk_gemm_kernel(const float* __restrict__ bq, const float* __restrict__ bk)
{
    if (blockIdx.z == 0)
        gemm_core(g_Hhi, g_Hlo, g_Wqhi, g_Wqlo, bq, QK_SCALE, nullptr, g_Qh, g_Ql);
    else
        gemm_core(g_Hhi, g_Hlo, g_Wkhi, g_Wklo, bk, 1.0f, nullptr, g_Kh, g_Kl);
}

__global__ __launch_bounds__(256, 2)
void out_gemm_kernel(const float* __restrict__ bo, float* __restrict__ out)
{
    gemm_core(g_AOh, g_AOl, g_Wohi, g_Wolo, bo, 1.0f, out, nullptr, nullptr);
}

// ---------------------------------------------------------------------------
// HMMA flash attention, fp16: QK^T 3-pass, PV 2-pass (P single fp16).
// grid (32 = B*NH, 16 = SEQ/128), 256 threads (8 warps), 128 q-rows per CTA.
// ---------------------------------------------------------------------------
#define SLDT 72                        // 144 B row (9 x 16B)
#define ATILE (64 * SLDT * 2)          // 9216 B per array
#define AST   (4 * ATILE)              // 36864 B per stage

__global__ __launch_bounds__(256, 1)
void attn_mma_kernel()
{
    extern __shared__ char dsm[];
    __half* pool = (__half*)dsm;

    const int tid = threadIdx.x;
    const int wid = tid >> 5;
    const int lid = tid & 31;
    const int b   = blockIdx.x >> 4;
    const int h   = blockIdx.x & 15;
    const int q0  = blockIdx.y * 128;

    const int lr    = lid & 7;
    const int half2_ = (lid >> 3) & 1;
    const int kh    = (lid >> 4) & 1;

    const uint32_t smem_base = smem_to_u32(dsm);

    // ---- stage Q tile (128 x 64, hi/lo) through stage-0 area, extract frags ----
#pragma unroll
    for (int i = 0; i < 8; i++) {
        int e   = tid + i * 256;
        int arr = e >> 10;
        int rem = e & 1023;
        int row = rem >> 3;
        int c   = rem & 7;
        const __half* src = (arr ? g_Ql : g_Qh)
            + (size_t)(b * SEQ + q0 + row) * D_MODEL + h * HDIM + c * 8;
        *(uint4*)(pool + arr * 128 * SLDT + row * SLDT + c * 8) = *(const uint4*)src;
    }
    __syncthreads();

    uint32_t qh[4][4], ql[4][4];
    {
        const int wr = wid * 16;
        const uint32_t uQh = smem_base;
        const uint32_t uQl = smem_base + 128 * SLDT * 2;
#pragma unroll
        for (int kc = 0; kc < 4; kc++) {
            int row = wr + lr + 8 * half2_;
            int col = kc * 16 + kh * 8;
            ldsm_x4(qh[kc][0], qh[kc][1], qh[kc][2], qh[kc][3],
                    uQh + (uint32_t)(row * SLDT + col) * 2);
            ldsm_x4(ql[kc][0], ql[kc][1], ql[kc][2], ql[kc][3],
                    uQl + (uint32_t)(row * SLDT + col) * 2);
        }
    }
    __syncthreads();

    float oacc[8][4];
#pragma unroll
    for (int nt = 0; nt < 8; nt++)
#pragma unroll
        for (int c = 0; c < 4; c++) oacc[nt][c] = 0.0f;
    float mx0 = -1e30f, mx1 = -1e30f, l0 = 0.0f, l1 = 0.0f;

    auto load_stage = [&](int kt, int s) {
        const int kb = kt * 64;
        uint32_t sb = smem_base + s * AST;
#pragma unroll
        for (int i = 0; i < 8; i++) {
            int arr = i >> 1;
            int rem = ((i & 1) << 8) + tid;
            int row = rem >> 3;
            int c   = rem & 7;
            const __half* g =
                (arr == 0 ? g_Kh : arr == 1 ? g_Kl : arr == 2 ? g_Hhi : g_Hlo)
                + (size_t)(b * SEQ + kb + row) * D_MODEL + h * HDIM + c * 8;
            cp16(sb + arr * ATILE + row * (SLDT * 2) + c * 16, g);
        }
        CP_COMMIT();
    };

    load_stage(0, 0);

    for (int kt = 0; kt < SEQ / 64; kt++) {
        const int s = kt & 1;
        CP_WAIT0();
        __syncthreads();
        if (kt + 1 < SEQ / 64) load_stage(kt + 1, s ^ 1);

        const uint32_t sb  = smem_base + s * AST;
        const uint32_t uKh = sb;
        const uint32_t uKl = sb + ATILE;
        const uint32_t uVh = sb + 2 * ATILE;
        const uint32_t uVl = sb + 3 * ATILE;

        // ---- S = Q K^T (3-pass fp16) ----
        float S[8][4];
#pragma unroll
        for (int nt = 0; nt < 8; nt++)
#pragma unroll
            for (int c = 0; c < 4; c++) S[nt][c] = 0.0f;

#pragma unroll
        for (int kc = 0; kc < 4; kc++) {
            uint32_t kbh[8][2], kbl[8][2];
#pragma unroll
            for (int ng = 0; ng < 4; ng++) {
                int row = ng * 16 + lr + 8 * half2_;
                int col = kc * 16 + kh * 8;
                uint32_t r0, r1, r2, r3;
                ldsm_x4(r0, r1, r2, r3, uKh + (uint32_t)(row * SLDT + col) * 2);
                kbh[ng * 2 + 0][0] = r0; kbh[ng * 2 + 0][1] = r2;
                kbh[ng * 2 + 1][0] = r1; kbh[ng * 2 + 1][1] = r3;
                ldsm_x4(r0, r1, r2, r3, uKl + (uint32_t)(row * SLDT + col) * 2);
                kbl[ng * 2 + 0][0] = r0; kbl[ng * 2 + 0][1] = r2;
                kbl[ng * 2 + 1][0] = r1; kbl[ng * 2 + 1][1] = r3;
            }
#pragma unroll
            for (int nt = 0; nt < 8; nt++) {
                mma16816(S[nt], qh[kc], kbh[nt]);
                mma16816(S[nt], qh[kc], kbl[nt]);
                mma16816(S[nt], ql[kc], kbh[nt]);
            }
        }

        // ---- online softmax ----
        float tm0 = -1e30f, tm1 = -1e30f;
#pragma unroll
        for (int nt = 0; nt < 8; nt++) {
            tm0 = fmaxf(tm0, fmaxf(S[nt][0], S[nt][1]));
            tm1 = fmaxf(tm1, fmaxf(S[nt][2], S[nt][3]));
        }
        tm0 = fmaxf(tm0, __shfl_xor_sync(0xffffffffu, tm0, 1));
        tm0 = fmaxf(tm0, __shfl_xor_sync(0xffffffffu, tm0, 2));
        tm1 = fmaxf(tm1, __shfl_xor_sync(0xffffffffu, tm1, 1));
        tm1 = fmaxf(tm1, __shfl_xor_sync(0xffffffffu, tm1, 2));
        float mn0 = fmaxf(mx0, tm0), mn1 = fmaxf(mx1, tm1);
        float a0 = ex2f(mx0 - mn0), a1 = ex2f(mx1 - mn1);

        // ---- P (single fp16 fragments) ----
        uint32_t pa[4][4];
        float rs0 = 0.0f, rs1 = 0.0f;
#pragma unroll
        for (int j = 0; j < 4; j++) {
#pragma unroll
            for (int sg = 0; sg < 2; sg++) {
                int t2 = j * 2 + sg;
                float p0 = ex2f(S[t2][0] - mn0);
                float p1 = ex2f(S[t2][1] - mn0);
                float p2 = ex2f(S[t2][2] - mn1);
                float p3 = ex2f(S[t2][3] - mn1);
                rs0 += p0 + p1;
                rs1 += p2 + p3;
                pa[j][sg * 2 + 0] = packh2(p0, p1);
                pa[j][sg * 2 + 1] = packh2(p2, p3);
            }
        }
        rs0 += __shfl_xor_sync(0xffffffffu, rs0, 1);
        rs0 += __shfl_xor_sync(0xffffffffu, rs0, 2);
        rs1 += __shfl_xor_sync(0xffffffffu, rs1, 1);
        rs1 += __shfl_xor_sync(0xffffffffu, rs1, 2);
        l0 = l0 * a0 + rs0;
        l1 = l1 * a1 + rs1;
        mx0 = mn0; mx1 = mn1;
#pragma unroll
        for (int nt = 0; nt < 8; nt++) {
            oacc[nt][0] *= a0; oacc[nt][1] *= a0;
            oacc[nt][2] *= a1; oacc[nt][3] *= a1;
        }

        // ---- O += P V (2-pass: P x Vhi + P x Vlo) ----
#pragma unroll
        for (int kc = 0; kc < 4; kc++) {
            uint32_t vbh[8][2], vbl[8][2];
#pragma unroll
            for (int dg = 0; dg < 4; dg++) {
                int rowk = kc * 16 + lr + 8 * half2_;
                int dimc = dg * 16 + kh * 8;
                uint32_t r0, r1, r2, r3;
                ldsm_x4_t(r0, r1, r2, r3, uVh + (uint32_t)(rowk * SLDT + dimc) * 2);
                vbh[dg * 2 + 0][0] = r0; vbh[dg * 2 + 0][1] = r1;
                vbh[dg * 2 + 1][0] = r2; vbh[dg * 2 + 1][1] = r3;
                ldsm_x4_t(r0, r1, r2, r3, uVl + (uint32_t)(rowk * SLDT + dimc) * 2);
                vbl[dg * 2 + 0][0] = r0; vbl[dg * 2 + 0][1] = r1;
                vbl[dg * 2 + 1][0] = r2; vbl[dg * 2 + 1][1] = r3;
            }
#pragma unroll
            for (int nt = 0; nt < 8; nt++) {
                mma16816(oacc[nt], pa[kc], vbh[nt]);
                mma16816(oacc[nt], pa[kc], vbl[nt]);
            }
        }
    }

    // ---- epilogue: normalize, fp16 hi/lo split, store ----
    const float inv0 = 1.0f / l0;
    const float inv1 = 1.0f / l1;
    const int gr  = b * SEQ + q0 + wid * 16 + (lid >> 2);
    const int col = h * HDIM + (lid & 3) * 2;
#pragma unroll
    for (int nt = 0; nt < 8; nt++) {
        int gc = col + nt * 8;
        float v0 = oacc[nt][0] * inv0, v1 = oacc[nt][1] * inv0;
        float v2 = oacc[nt][2] * inv1, v3 = oacc[nt][3] * inv1;
        __half h0 = __float2half_rn(v0), h1 = __float2half_rn(v1);
        __half h2 = __float2half_rn(v2), h3 = __float2half_rn(v3);
        *(uint32_t*)&g_AOh[(size_t)gr * D_MODEL + gc] =
            (uint32_t)__half_as_ushort(h0) | ((uint32_t)__half_as_ushort(h1) << 16);
        *(uint32_t*)&g_AOl[(size_t)gr * D_MODEL + gc] =
            packh2(v0 - __half2float(h0), v1 - __half2float(h1));
        *(uint32_t*)&g_AOh[(size_t)(gr + 8) * D_MODEL + gc] =
            (uint32_t)__half_as_ushort(h2) | ((uint32_t)__half_as_ushort(h3) << 16);
        *(uint32_t*)&g_AOl[(size_t)(gr + 8) * D_MODEL + gc] =
            packh2(v2 - __half2float(h2), v3 - __half2float(h3));
    }
}

// ---------------------------------------------------------------------------
extern "C" void kernel_launch(void* const* d_in, const int* in_sizes, int n_in,
                              void* d_out, int out_size)
{
    (void)in_sizes; (void)n_in; (void)out_size;
    const float* H  = (const float*)d_in[0];
    const float* Wq = (const float*)d_in[1];
    const float* bq = (const float*)d_in[2];
    const float* Wk = (const float*)d_in[3];
    const float* bk = (const float*)d_in[4];
    const float* Wo = (const float*)d_in[5];
    const float* bo = (const float*)d_in[6];
    float* out = (float*)d_out;

    void *p_Hhi, *p_Hlo;
    void *p_Wqhi, *p_Wqlo, *p_Wkhi, *p_Wklo, *p_Wohi, *p_Wolo;
    cudaGetSymbolAddress(&p_Hhi,  g_Hhi);  cudaGetSymbolAddress(&p_Hlo,  g_Hlo);
    cudaGetSymbolAddress(&p_Wqhi, g_Wqhi); cudaGetSymbolAddress(&p_Wqlo, g_Wqlo);
    cudaGetSymbolAddress(&p_Wkhi, g_Wkhi); cudaGetSymbolAddress(&p_Wklo, g_Wklo);
    cudaGetSymbolAddress(&p_Wohi, g_Wohi); cudaGetSymbolAddress(&p_Wolo, g_Wolo);

    cudaFuncSetAttribute(qk_gemm_kernel,
                         cudaFuncAttributeMaxDynamicSharedMemorySize, 2 * GST);
    cudaFuncSetAttribute(out_gemm_kernel,
                         cudaFuncAttributeMaxDynamicSharedMemorySize, 2 * GST);
    cudaFuncSetAttribute(attn_mma_kernel,
                         cudaFuncAttributeMaxDynamicSharedMemorySize, 2 * AST);

    const int nH4 = NROWS * D_MODEL / 4;      // 1,048,576
    const int nW4 = D_MODEL * D_MODEL / 4;    // 262,144
    const int nTot = nH4 + 3 * nW4;           // 1,835,008

    split4_kernel<<<(nTot + 255) / 256, 256>>>(
        (const float4*)H,  (uint2*)p_Hhi,  (uint2*)p_Hlo,  nH4,
        (const float4*)Wq, (uint2*)p_Wqhi, (uint2*)p_Wqlo, nW4,
        (const float4*)Wk, (uint2*)p_Wkhi, (uint2*)p_Wklo, nW4,
        (const float4*)Wo, (uint2*)p_Wohi, (uint2*)p_Wolo, nW4);

    dim3 ggrid(D_MODEL / BN, NROWS / BM, 2);   // (8, 32, 2)
    qk_gemm_kernel<<<ggrid, 256, 2 * GST>>>(bq, bk);

    dim3 agrid(BATCH * NHEADS, SEQ / 128);     // (32, 16)
    attn_mma_kernel<<<agrid, 256, 2 * AST>>>();

    dim3 ogrid(D_MODEL / BN, NROWS / BM, 1);   // (8, 32)
    out_gemm_kernel<<<ogrid, 256, 2 * GST>>>(bo, out);
}